// round 9
// baseline (speedup 1.0000x reference)
#include <cuda_runtime.h>
#include <cuda_bf16.h>
#include <cstdint>
#include <cstddef>

#define NB 32
#define LQ 64
#define LV 128
#define QS 512
#define FS 1024
#define BN 512

// ---------------- scratch (device globals — no allocation) ----------------
// Wh/Uv stored TRANSPOSED per batch: WhT[b][n][q], UvT[b][n][v]
__device__ float g_WhT[(size_t)NB * BN * LQ];
__device__ float g_UvT[(size_t)NB * BN * LV];
__device__ __nv_bfloat16 g_phr_hi[(size_t)NB * LQ * QS];
__device__ __nv_bfloat16 g_phr_lo[(size_t)NB * LQ * QS];
__device__ __nv_bfloat16 g_vis_hi[(size_t)NB * LV * FS];
__device__ __nv_bfloat16 g_vis_lo[(size_t)NB * LV * FS];
__device__ __nv_bfloat16 g_W_hi[(size_t)BN * QS];
__device__ __nv_bfloat16 g_W_lo[(size_t)BN * QS];
__device__ __nv_bfloat16 g_U_hi[(size_t)BN * FS];
__device__ __nv_bfloat16 g_U_lo[(size_t)BN * FS];
__device__ __nv_bfloat16 g_wt_hi[(size_t)NB * LQ * LV];
__device__ __nv_bfloat16 g_wt_lo[(size_t)NB * LQ * LV];

// ---------------------------------------------------------------------------
// Helpers
// ---------------------------------------------------------------------------
__device__ __forceinline__ uint32_t smem_u32(const void* p) {
    return (uint32_t)__cvta_generic_to_shared(p);
}

__device__ __forceinline__ void cpasync16(void* s, const void* g) {
    asm volatile("cp.async.cg.shared.global [%0], [%1], 16;"
                 :: "r"(smem_u32(s)), "l"(g));
}

__device__ __forceinline__ void ldsm_x4(uint32_t& r0, uint32_t& r1,
                                        uint32_t& r2, uint32_t& r3, uint32_t addr) {
    asm volatile("ldmatrix.sync.aligned.m8n8.x4.shared.b16 {%0,%1,%2,%3}, [%4];"
                 : "=r"(r0), "=r"(r1), "=r"(r2), "=r"(r3) : "r"(addr));
}

__device__ __forceinline__ void ldsm_x4_t(uint32_t& r0, uint32_t& r1,
                                          uint32_t& r2, uint32_t& r3, uint32_t addr) {
    asm volatile("ldmatrix.sync.aligned.m8n8.x4.trans.shared.b16 {%0,%1,%2,%3}, [%4];"
                 : "=r"(r0), "=r"(r1), "=r"(r2), "=r"(r3) : "r"(addr));
}

__device__ __forceinline__ void mma_bf16(float* d, const uint32_t* a, const uint32_t* b) {
    asm volatile(
        "mma.sync.aligned.m16n8k16.row.col.f32.bf16.bf16.f32 "
        "{%0,%1,%2,%3}, {%4,%5,%6,%7}, {%8,%9}, {%0,%1,%2,%3};"
        : "+f"(d[0]), "+f"(d[1]), "+f"(d[2]), "+f"(d[3])
        : "r"(a[0]), "r"(a[1]), "r"(a[2]), "r"(a[3]), "r"(b[0]), "r"(b[1]));
}

// Hardware tanh: 1 MUFU op, rel err ~2^-11 (validated: net rel_err 5e-6)
__device__ __forceinline__ float tanh_fast(float x) {
    float y;
    asm("tanh.approx.f32 %0, %1;" : "=f"(y) : "f"(x));
    return y;
}

// ---------------------------------------------------------------------------
// Split pass: fp32 -> (hi, lo) bf16 for 4 arrays; also copies phr into the
// concat output columns [0, QS).
// ---------------------------------------------------------------------------
__global__ __launch_bounds__(256) void split4_kernel(
    const float* __restrict__ s0, __nv_bfloat16* __restrict__ h0, __nv_bfloat16* __restrict__ l0, int n0,
    const float* __restrict__ s1, __nv_bfloat16* __restrict__ h1, __nv_bfloat16* __restrict__ l1, int n1,
    const float* __restrict__ s2, __nv_bfloat16* __restrict__ h2, __nv_bfloat16* __restrict__ l2, int n2,
    const float* __restrict__ s3, __nv_bfloat16* __restrict__ h3, __nv_bfloat16* __restrict__ l3, int n3,
    float* __restrict__ out_sem)
{
    int i = blockIdx.x * 256 + threadIdx.x;
    const float* s; __nv_bfloat16 *h, *l; int idx;
    bool is_phr = false;
    if (i < n0)                { s = s0; h = h0; l = l0; idx = i; is_phr = true; }
    else if (i < n0 + n1)      { s = s1; h = h1; l = l1; idx = i - n0; }
    else if (i < n0 + n1 + n2) { s = s2; h = h2; l = l2; idx = i - n0 - n1; }
    else                       { s = s3; h = h3; l = l3; idx = i - n0 - n1 - n2; }

    float4 v = reinterpret_cast<const float4*>(s)[idx];
    __nv_bfloat162 ha, hb, la, lb;
    ha.x = __float2bfloat16(v.x); ha.y = __float2bfloat16(v.y);
    hb.x = __float2bfloat16(v.z); hb.y = __float2bfloat16(v.w);
    la.x = __float2bfloat16(v.x - __bfloat162float(ha.x));
    la.y = __float2bfloat16(v.y - __bfloat162float(ha.y));
    lb.x = __float2bfloat16(v.z - __bfloat162float(hb.x));
    lb.y = __float2bfloat16(v.w - __bfloat162float(hb.y));
    reinterpret_cast<__nv_bfloat162*>(h)[2 * idx]     = ha;
    reinterpret_cast<__nv_bfloat162*>(h)[2 * idx + 1] = hb;
    reinterpret_cast<__nv_bfloat162*>(l)[2 * idx]     = la;
    reinterpret_cast<__nv_bfloat162*>(l)[2 * idx + 1] = lb;

    if (is_phr) {
        const size_t row = (size_t)idx >> 7;
        const int col = (idx & 127) << 2;
        *reinterpret_cast<float4*>(&out_sem[row * (QS + FS) + col]) = v;
    }
}

// ---------------------------------------------------------------------------
// Tensor-core NT GEMM, 128x128 block tile (pre-split bf16 hi/lo, cp.async
// 2-stage), transposed epilogue CT[b][n][m_local]. Both problems, ONE launch.
// 8 warps in 4x2 grid, warp tile 32x64. B fragments via ldsm_x4 (2 n-groups
// x 2 k-halves per op) -> LSU:tensor ~1.3:1 (was 3:1).
// ---------------------------------------------------------------------------
#define APITCH 40
#define KC 32
#define GSTAGE (512 * APITCH)   // Ah/Al/Bh/Bl, 128 rows each

__device__ __forceinline__ void gemm_issue_stage(
    __nv_bfloat16* smem, int st, int tid, int m0, int n0, int k0, int K,
    const __nv_bfloat16* Ahi, const __nv_bfloat16* Alo,
    const __nv_bfloat16* Bhi, const __nv_bfloat16* Blo)
{
    __nv_bfloat16* base = smem + st * GSTAGE;
#pragma unroll
    for (int e = 0; e < 2; e++) {
        int idx = tid + e * 256;
        int row = idx >> 2, c = (idx & 3) * 8;
        cpasync16(&base[row * APITCH + c],
                  &Ahi[(size_t)(m0 + row) * K + k0 + c]);
        cpasync16(&base[128 * APITCH + row * APITCH + c],
                  &Alo[(size_t)(m0 + row) * K + k0 + c]);
        cpasync16(&base[256 * APITCH + row * APITCH + c],
                  &Bhi[(size_t)(n0 + row) * K + k0 + c]);
        cpasync16(&base[384 * APITCH + row * APITCH + c],
                  &Blo[(size_t)(n0 + row) * K + k0 + c]);
    }
    asm volatile("cp.async.commit_group;");
}

__device__ __forceinline__ void gemm_body_T(
    __nv_bfloat16* gsm,
    const __nv_bfloat16* __restrict__ Ahi, const __nv_bfloat16* __restrict__ Alo,
    const __nv_bfloat16* __restrict__ Bhi, const __nv_bfloat16* __restrict__ Blo,
    const float* __restrict__ bias, float* __restrict__ CT,
    int K, int bshift, int m0, int n0)
{
    const int tid = threadIdx.x;
    const int lane = tid & 31;
    const int wid = tid >> 5;
    const int wm = wid >> 1;        // 0..3 (32 m-rows each)
    const int wn = wid & 1;         // 0..1 (64 n-cols each)
    const int width = 1 << bshift;
    const int wmask = width - 1;

    const int lq = lane >> 3;
    const int lr = lane & 7;

    float acc[2][8][4];
#pragma unroll
    for (int i = 0; i < 2; i++)
#pragma unroll
        for (int j = 0; j < 8; j++)
#pragma unroll
            for (int r = 0; r < 4; r++) acc[i][j][r] = 0.0f;

    const int NC = K / KC;
    gemm_issue_stage(gsm, 0, tid, m0, n0, 0, K, Ahi, Alo, Bhi, Blo);

    for (int c = 0; c < NC; c++) {
        const int st = c & 1;
        if (c + 1 < NC) {
            gemm_issue_stage(gsm, st ^ 1, tid, m0, n0, (c + 1) * KC, K,
                             Ahi, Alo, Bhi, Blo);
            asm volatile("cp.async.wait_group 1;" ::: "memory");
        } else {
            asm volatile("cp.async.wait_group 0;" ::: "memory");
        }
        __syncthreads();

        const __nv_bfloat16* Ah_s = gsm + st * GSTAGE;
        const __nv_bfloat16* Al_s = Ah_s + 128 * APITCH;
        const __nv_bfloat16* Bh_s = Ah_s + 256 * APITCH;
        const __nv_bfloat16* Bl_s = Ah_s + 384 * APITCH;

#pragma unroll
        for (int ks = 0; ks < KC; ks += 16) {
            uint32_t ah[2][4], al[2][4];
#pragma unroll
            for (int ma = 0; ma < 2; ma++) {
                const int m_local = wm * 32 + ma * 16 + (lq & 1) * 8 + lr;
                const int k_local = ks + (lq >> 1) * 8;
                ldsm_x4(ah[ma][0], ah[ma][1], ah[ma][2], ah[ma][3],
                        smem_u32(&Ah_s[m_local * APITCH + k_local]));
                ldsm_x4(al[ma][0], al[ma][1], al[ma][2], al[ma][3],
                        smem_u32(&Al_s[m_local * APITCH + k_local]));
            }
            // B: 8 n-groups of 8; one ldsm_x4 covers 2 groups x 2 k-halves
            uint32_t bh[8][2], bl[8][2];
#pragma unroll
            for (int nb = 0; nb < 4; nb++) {
                const int n_local = wn * 64 + nb * 16 + (lq >> 1) * 8 + lr;
                const int k_local = ks + (lq & 1) * 8;
                uint32_t r0, r1, r2, r3;
                ldsm_x4(r0, r1, r2, r3,
                        smem_u32(&Bh_s[n_local * APITCH + k_local]));
                bh[2 * nb][0] = r0; bh[2 * nb][1] = r1;
                bh[2 * nb + 1][0] = r2; bh[2 * nb + 1][1] = r3;
                ldsm_x4(r0, r1, r2, r3,
                        smem_u32(&Bl_s[n_local * APITCH + k_local]));
                bl[2 * nb][0] = r0; bl[2 * nb][1] = r1;
                bl[2 * nb + 1][0] = r2; bl[2 * nb + 1][1] = r3;
            }
#pragma unroll
            for (int ma = 0; ma < 2; ma++)
#pragma unroll
                for (int na = 0; na < 8; na++) {
                    mma_bf16(acc[ma][na], ah[ma], bh[na]);
                    mma_bf16(acc[ma][na], ah[ma], bl[na]);
                    mma_bf16(acc[ma][na], al[ma], bh[na]);
                }
        }
        __syncthreads();
    }

    const int er = lane >> 2;
    const int ec = (lane & 3) << 1;
#pragma unroll
    for (int ma = 0; ma < 2; ma++) {
        const int mbase = m0 + wm * 32 + ma * 16;
#pragma unroll
        for (int na = 0; na < 8; na++) {
            const int nbase = n0 + wn * 64 + na * 8 + ec;
            float b0 = 0.0f, b1 = 0.0f;
            if (bias) { b0 = bias[nbase]; b1 = bias[nbase + 1]; }
#pragma unroll
            for (int rr = 0; rr < 2; rr++) {
                const int m = mbase + er + 8 * rr;
                const size_t base = ((size_t)(m >> bshift) * BN) * width
                                    + (m & wmask);
                CT[base + (size_t)nbase * width]       = acc[ma][na][2 * rr]     + b0;
                CT[base + (size_t)(nbase + 1) * width] = acc[ma][na][2 * rr + 1] + b1;
            }
        }
    }
}

// One launch, 48 y-tiles: y<32 -> Uv (K=1024, longer, scheduled first),
// y>=32 -> Wh (K=512). x: 4 n-tiles of 128.
__global__ __launch_bounds__(256, 1) void gemm_dual_T(
    const __nv_bfloat16* __restrict__ A0h, const __nv_bfloat16* __restrict__ A0l,
    const __nv_bfloat16* __restrict__ B0h, const __nv_bfloat16* __restrict__ B0l,
    float* __restrict__ C0T,                        // UvT
    const __nv_bfloat16* __restrict__ A1h, const __nv_bfloat16* __restrict__ A1l,
    const __nv_bfloat16* __restrict__ B1h, const __nv_bfloat16* __restrict__ B1l,
    const float* __restrict__ bias1, float* __restrict__ C1T)  // WhT
{
    extern __shared__ __nv_bfloat16 gsm[];
    if ((int)blockIdx.y < 32) {
        gemm_body_T(gsm, A0h, A0l, B0h, B0l, nullptr, C0T, FS, 7,
                    blockIdx.y * 128, blockIdx.x * 128);
    } else {
        gemm_body_T(gsm, A1h, A1l, B1h, B1l, bias1, C1T, QS, 6,
                    (blockIdx.y - 32) * 128, blockIdx.x * 128);
    }
}

// ---------------------------------------------------------------------------
// Fused energies + softmax, v-split for occupancy.
// Block: 512 threads = 16 warps. warp = (q 0..7, vhalf 0..1); lane owns
// v = vhalf*64 + 2*lane + {0,1}.
// ---------------------------------------------------------------------------
#define QT 8
#define ECH 32
#define NCHUNK (BN / ECH)

__global__ __launch_bounds__(512) void energy_softmax_kernel(
    const float* __restrict__ WhT, const float* __restrict__ UvT,
    const float* __restrict__ w,
    float* __restrict__ energies, float* __restrict__ weights,
    __nv_bfloat16* __restrict__ wt_hi, __nv_bfloat16* __restrict__ wt_lo)
{
    __shared__ alignas(16) float Cs[2][ECH][LV];
    __shared__ alignas(16) float As[2][ECH][QT];
    __shared__ float ws[BN];
    __shared__ alignas(16) float red[QT][LV];

    const int b = blockIdx.y;
    const int q0 = blockIdx.x * QT;
    const int tid = threadIdx.x;
    const int lane = tid & 31;
    const int wid = tid >> 5;
    const int ql = wid >> 1;
    const int vh = wid & 1;
    const int v0 = vh * 64 + 2 * lane;

    const float* AbT = WhT + (size_t)b * BN * LQ;
    const float* CbT = UvT + (size_t)b * BN * LV;

    for (int i = tid; i < BN; i += 512) ws[i] = w[i];

    auto issue = [&](int c) {
        const int buf = c & 1;
        const int n0 = c * ECH;
#pragma unroll
        for (int e = 0; e < 2; e++) {
            const int o = tid + e * 512;
            const int row = o >> 5, col = (o & 31) * 4;
            cpasync16(&Cs[buf][row][col], &CbT[(size_t)(n0 + row) * LV + col]);
        }
        if (tid < 64) {
            const int row = tid >> 1, half = tid & 1;
            cpasync16(&As[buf][row][half * 4],
                      &AbT[(size_t)(n0 + row) * LQ + q0 + half * 4]);
        }
        asm volatile("cp.async.commit_group;");
    };

    float acc0 = 0.0f, acc1 = 0.0f;

    issue(0);
    for (int c = 0; c < NCHUNK; c++) {
        if (c + 1 < NCHUNK) {
            issue(c + 1);
            asm volatile("cp.async.wait_group 1;" ::: "memory");
        } else {
            asm volatile("cp.async.wait_group 0;" ::: "memory");
        }
        __syncthreads();
        const int buf = c & 1;
        const int nb = c * ECH;
#pragma unroll
        for (int kk = 0; kk < ECH; kk++) {
            const float a = As[buf][kk][ql];
            const float wn = ws[nb + kk];
            const float2 cv = *reinterpret_cast<const float2*>(
                &Cs[buf][kk][v0]);
            acc0 += wn * tanh_fast(a + cv.x);
            acc1 += wn * tanh_fast(a + cv.y);
        }
        __syncthreads();
    }

    red[ql][v0] = acc0;
    red[ql][v0 + 1] = acc1;
    __syncthreads();

    if (vh == 0) {
        const float4 a4 = *reinterpret_cast<const float4*>(&red[ql][4 * lane]);
        float acc[4] = {a4.x, a4.y, a4.z, a4.w};

        float mx = fmaxf(fmaxf(acc[0], acc[1]), fmaxf(acc[2], acc[3]));
#pragma unroll
        for (int o = 16; o > 0; o >>= 1)
            mx = fmaxf(mx, __shfl_xor_sync(0xFFFFFFFFu, mx, o));
        float ex[4], s = 0.0f;
#pragma unroll
        for (int j = 0; j < 4; j++) { ex[j] = __expf(acc[j] - mx); s += ex[j]; }
#pragma unroll
        for (int o = 16; o > 0; o >>= 1)
            s += __shfl_xor_sync(0xFFFFFFFFu, s, o);
        const float inv = __fdividef(1.0f, s);

        const size_t row = (size_t)b * LQ + q0 + ql;
        const size_t off = row * LV + 4 * lane;

        float4 e4; e4.x = acc[0]; e4.y = acc[1]; e4.z = acc[2]; e4.w = acc[3];
        *reinterpret_cast<float4*>(&energies[off]) = e4;

        float wv[4];
#pragma unroll
        for (int j = 0; j < 4; j++) wv[j] = ex[j] * inv;
        float4 w4; w4.x = wv[0]; w4.y = wv[1]; w4.z = wv[2]; w4.w = wv[3];
        *reinterpret_cast<float4*>(&weights[off]) = w4;

        __nv_bfloat162 h01, h23, l01, l23;
        h01.x = __float2bfloat16(wv[0]); h01.y = __float2bfloat16(wv[1]);
        h23.x = __float2bfloat16(wv[2]); h23.y = __float2bfloat16(wv[3]);
        l01.x = __float2bfloat16(wv[0] - __bfloat162float(h01.x));
        l01.y = __float2bfloat16(wv[1] - __bfloat162float(h01.y));
        l23.x = __float2bfloat16(wv[2] - __bfloat162float(h23.x));
        l23.y = __float2bfloat16(wv[3] - __bfloat162float(h23.y));
        uint2 hh, ll;
        hh.x = *reinterpret_cast<uint32_t*>(&h01);
        hh.y = *reinterpret_cast<uint32_t*>(&h23);
        ll.x = *reinterpret_cast<uint32_t*>(&l01);
        ll.y = *reinterpret_cast<uint32_t*>(&l23);
        *reinterpret_cast<uint2*>(&wt_hi[off]) = hh;
        *reinterpret_cast<uint2*>(&wt_lo[off]) = ll;
    }
}

// ---------------------------------------------------------------------------
// Tensor-core aligned: out[b,q,QS+f] = sum_v weights[b,q,v] * vis[b,v,f]
// ---------------------------------------------------------------------------
#define WPITCH 136

__global__ __launch_bounds__(256) void aligned_tc_kernel(
    const __nv_bfloat16* __restrict__ wt_hi, const __nv_bfloat16* __restrict__ wt_lo,
    const __nv_bfloat16* __restrict__ vis_hi, const __nv_bfloat16* __restrict__ vis_lo,
    float* __restrict__ out_sem)
{
    extern __shared__ __nv_bfloat16 asm_[];
    __nv_bfloat16* Wh_s = asm_;
    __nv_bfloat16* Wl_s = asm_ + 64 * WPITCH;
    __nv_bfloat16* Vh_s = asm_ + 128 * WPITCH;
    __nv_bfloat16* Vl_s = asm_ + 256 * WPITCH;

    const int b = blockIdx.y;
    const int f0 = blockIdx.x * 128;
    const int tid = threadIdx.x;
    const int lane = tid & 31;
    const int wid = tid >> 5;
    const int wm = wid >> 2;
    const int wn = wid & 3;
    const int lq = lane >> 3;
    const int lr = lane & 7;

#pragma unroll
    for (int e = 0; e < 4; e++) {
        int idx = tid + e * 256;
        int row = idx >> 4, c = (idx & 15) * 8;
        cpasync16(&Wh_s[row * WPITCH + c], &wt_hi[((size_t)b * LQ + row) * LV + c]);
        cpasync16(&Wl_s[row * WPITCH + c], &wt_lo[((size_t)b * LQ + row) * LV + c]);
    }
#pragma unroll
    for (int e = 0; e < 8; e++) {
        int idx = tid + e * 256;
        int row = idx >> 4, c = (idx & 15) * 8;
        cpasync16(&Vh_s[row * WPITCH + c],
                  &vis_hi[((size_t)b * LV + row) * FS + f0 + c]);
        cpasync16(&Vl_s[row * WPITCH + c],
                  &vis_lo[((size_t)b * LV + row) * FS + f0 + c]);
    }
    asm volatile("cp.async.commit_group;");
    asm volatile("cp.async.wait_group 0;" ::: "memory");
    __syncthreads();

    float acc[2][4][4];
#pragma unroll
    for (int i = 0; i < 2; i++)
#pragma unroll
        for (int j = 0; j < 4; j++)
#pragma unroll
            for (int r = 0; r < 4; r++) acc[i][j][r] = 0.0f;

#pragma unroll
    for (int ks = 0; ks < 8; ks++) {
        uint32_t ah[2][4], al[2][4];
#pragma unroll
        for (int ma = 0; ma < 2; ma++) {
            const int m_local = wm * 32 + ma * 16 + (lq & 1) * 8 + lr;
            const int k_local = ks * 16 + (lq >> 1) * 8;
            ldsm_x4(ah[ma][0], ah[ma][1], ah[ma][2], ah[ma][3],
                    smem_u32(&Wh_s[m_local * WPITCH + k_local]));
            ldsm_x4(al[ma][0], al[ma][1], al[ma][2], al[ma][3],
                    smem_u32(&Wl_s[m_local * WPITCH + k_local]));
        }
        uint32_t bh[4][2], bl[4][2];
#pragma unroll
        for (int np = 0; np < 2; np++) {
            const int krow = ks * 16 + (lq & 1) * 8 + lr;
            const int ncol = wn * 32 + np * 16 + (lq >> 1) * 8;
            uint32_t r0, r1, r2, r3;
            ldsm_x4_t(r0, r1, r2, r3, smem_u32(&Vh_s[krow * WPITCH + ncol]));
            bh[np * 2][0] = r0; bh[np * 2][1] = r1;
            bh[np * 2 + 1][0] = r2; bh[np * 2 + 1][1] = r3;
            ldsm_x4_t(r0, r1, r2, r3, smem_u32(&Vl_s[krow * WPITCH + ncol]));
            bl[np * 2][0] = r0; bl[np * 2][1] = r1;
            bl[np * 2 + 1][0] = r2; bl[np * 2 + 1][1] = r3;
        }
#pragma unroll
        for (int ma = 0; ma < 2; ma++)
#pragma unroll
            for (int na = 0; na < 4; na++) {
                mma_bf16(acc[ma][na], ah[ma], bh[na]);
                mma_bf16(acc[ma][na], ah[ma], bl[na]);
                mma_bf16(acc[ma][na], al[ma], bh[na]);
            }
    }

    const int er = lane >> 2;
    const int ec = (lane & 3) << 1;
#pragma unroll
    for (int ma = 0; ma < 2; ma++) {
        const int qbase = wm * 32 + ma * 16;
#pragma unroll
        for (int na = 0; na < 4; na++) {
            const int f = f0 + wn * 32 + na * 8 + ec;
            float2 v0, v1;
            v0.x = acc[ma][na][0]; v0.y = acc[ma][na][1];
            v1.x = acc[ma][na][2]; v1.y = acc[ma][na][3];
            *reinterpret_cast<float2*>(
                &out_sem[((size_t)b * LQ + qbase + er) * (QS + FS) + QS + f]) = v0;
            *reinterpret_cast<float2*>(
                &out_sem[((size_t)b * LQ + qbase + er + 8) * (QS + FS) + QS + f]) = v1;
        }
    }
}

extern "C" void kernel_launch(void* const* d_in, const int* in_sizes, int n_in,
                              void* d_out, int out_size)
{
    const float* phr  = (const float*)d_in[0];
    const float* vis  = (const float*)d_in[1];
    const float* W    = (const float*)d_in[2];
    const float* U    = (const float*)d_in[3];
    const float* bias = (const float*)d_in[4];
    const float* w    = (const float*)d_in[5];

    float* out = (float*)d_out;
    float* out_sem = out;
    float* out_w   = out + (size_t)NB * LQ * (QS + FS);
    float* out_e   = out_w + (size_t)NB * LQ * LV;

    float *WhT, *UvT;
    __nv_bfloat16 *phr_hi, *phr_lo, *vis_hi, *vis_lo, *W_hi, *W_lo, *U_hi, *U_lo;
    __nv_bfloat16 *wt_hi, *wt_lo;
    cudaGetSymbolAddress((void**)&WhT, g_WhT);
    cudaGetSymbolAddress((void**)&UvT, g_UvT);
    cudaGetSymbolAddress((void**)&phr_hi, g_phr_hi);
    cudaGetSymbolAddress((void**)&phr_lo, g_phr_lo);
    cudaGetSymbolAddress((void**)&vis_hi, g_vis_hi);
    cudaGetSymbolAddress((void**)&vis_lo, g_vis_lo);
    cudaGetSymbolAddress((void**)&W_hi, g_W_hi);
    cudaGetSymbolAddress((void**)&W_lo, g_W_lo);
    cudaGetSymbolAddress((void**)&U_hi, g_U_hi);
    cudaGetSymbolAddress((void**)&U_lo, g_U_lo);
    cudaGetSymbolAddress((void**)&wt_hi, g_wt_hi);
    cudaGetSymbolAddress((void**)&wt_lo, g_wt_lo);

    cudaFuncSetAttribute(gemm_dual_T,
                         cudaFuncAttributeMaxDynamicSharedMemorySize, 81920);
    cudaFuncSetAttribute(aligned_tc_kernel,
                         cudaFuncAttributeMaxDynamicSharedMemorySize, 104448);

    // split (+ phr concat copy)
    split4_kernel<<<5888, 256>>>(phr, phr_hi, phr_lo, 262144,
                                 vis, vis_hi, vis_lo, 1048576,
                                 W,   W_hi,   W_lo,   65536,
                                 U,   U_hi,   U_lo,   131072,
                                 out_sem);

    // Both GEMMs, one launch, 128x128 tiles
    // (Uv: y 0..31, K=1024; Wh: y 32..47, K=512; x: 4 n-tiles)
    gemm_dual_T<<<dim3(BN / 128, 48), 256, 81920>>>(
        vis_hi, vis_lo, U_hi, U_lo, UvT,
        phr_hi, phr_lo, W_hi, W_lo, bias, WhT);

    // energies + softmax (v-split, 512 threads)
    energy_softmax_kernel<<<dim3(LQ / QT, NB), 512>>>(WhT, UvT, w, out_e, out_w,
                                                      wt_hi, wt_lo);
    // aligned via tensor cores
    aligned_tc_kernel<<<dim3(FS / 128, NB), 256, 104448>>>(wt_hi, wt_lo,
                                                           vis_hi, vis_lo,
                                                           out_sem);
}

// round 10
// speedup vs baseline: 1.0762x; 1.0762x over previous
#include <cuda_runtime.h>
#include <cuda_bf16.h>
#include <cstdint>
#include <cstddef>

#define NB 32
#define LQ 64
#define LV 128
#define QS 512
#define FS 1024
#define BN 512

// ---------------- scratch (device globals — no allocation) ----------------
// Wh/Uv stored TRANSPOSED per batch: WhT[b][n][q], UvT[b][n][v]
__device__ float g_WhT[(size_t)NB * BN * LQ];
__device__ float g_UvT[(size_t)NB * BN * LV];
__device__ __nv_bfloat16 g_phr_hi[(size_t)NB * LQ * QS];
__device__ __nv_bfloat16 g_phr_lo[(size_t)NB * LQ * QS];
__device__ __nv_bfloat16 g_vis_hi[(size_t)NB * LV * FS];
__device__ __nv_bfloat16 g_vis_lo[(size_t)NB * LV * FS];
__device__ __nv_bfloat16 g_W_hi[(size_t)BN * QS];
__device__ __nv_bfloat16 g_W_lo[(size_t)BN * QS];
__device__ __nv_bfloat16 g_U_hi[(size_t)BN * FS];
__device__ __nv_bfloat16 g_U_lo[(size_t)BN * FS];
__device__ __nv_bfloat16 g_wt_hi[(size_t)NB * LQ * LV];
__device__ __nv_bfloat16 g_wt_lo[(size_t)NB * LQ * LV];

// ---------------------------------------------------------------------------
// Helpers
// ---------------------------------------------------------------------------
__device__ __forceinline__ uint32_t smem_u32(const void* p) {
    return (uint32_t)__cvta_generic_to_shared(p);
}

__device__ __forceinline__ void cpasync16(void* s, const void* g) {
    asm volatile("cp.async.cg.shared.global [%0], [%1], 16;"
                 :: "r"(smem_u32(s)), "l"(g));
}

__device__ __forceinline__ void ldsm_x4(uint32_t& r0, uint32_t& r1,
                                        uint32_t& r2, uint32_t& r3, uint32_t addr) {
    asm volatile("ldmatrix.sync.aligned.m8n8.x4.shared.b16 {%0,%1,%2,%3}, [%4];"
                 : "=r"(r0), "=r"(r1), "=r"(r2), "=r"(r3) : "r"(addr));
}

__device__ __forceinline__ void ldsm_x4_t(uint32_t& r0, uint32_t& r1,
                                          uint32_t& r2, uint32_t& r3, uint32_t addr) {
    asm volatile("ldmatrix.sync.aligned.m8n8.x4.trans.shared.b16 {%0,%1,%2,%3}, [%4];"
                 : "=r"(r0), "=r"(r1), "=r"(r2), "=r"(r3) : "r"(addr));
}

__device__ __forceinline__ void mma_bf16(float* d, const uint32_t* a, const uint32_t* b) {
    asm volatile(
        "mma.sync.aligned.m16n8k16.row.col.f32.bf16.bf16.f32 "
        "{%0,%1,%2,%3}, {%4,%5,%6,%7}, {%8,%9}, {%0,%1,%2,%3};"
        : "+f"(d[0]), "+f"(d[1]), "+f"(d[2]), "+f"(d[3])
        : "r"(a[0]), "r"(a[1]), "r"(a[2]), "r"(a[3]), "r"(b[0]), "r"(b[1]));
}

// Hardware tanh: 1 MUFU op, rel err ~2^-11 (validated: net rel_err 5e-6)
__device__ __forceinline__ float tanh_fast(float x) {
    float y;
    asm("tanh.approx.f32 %0, %1;" : "=f"(y) : "f"(x));
    return y;
}

// ---------------------------------------------------------------------------
// Split pass: fp32 -> (hi, lo) bf16 for 4 arrays; also copies phr into the
// concat output columns [0, QS).
// ---------------------------------------------------------------------------
__global__ __launch_bounds__(256) void split4_kernel(
    const float* __restrict__ s0, __nv_bfloat16* __restrict__ h0, __nv_bfloat16* __restrict__ l0, int n0,
    const float* __restrict__ s1, __nv_bfloat16* __restrict__ h1, __nv_bfloat16* __restrict__ l1, int n1,
    const float* __restrict__ s2, __nv_bfloat16* __restrict__ h2, __nv_bfloat16* __restrict__ l2, int n2,
    const float* __restrict__ s3, __nv_bfloat16* __restrict__ h3, __nv_bfloat16* __restrict__ l3, int n3,
    float* __restrict__ out_sem)
{
    int i = blockIdx.x * 256 + threadIdx.x;
    const float* s; __nv_bfloat16 *h, *l; int idx;
    bool is_phr = false;
    if (i < n0)                { s = s0; h = h0; l = l0; idx = i; is_phr = true; }
    else if (i < n0 + n1)      { s = s1; h = h1; l = l1; idx = i - n0; }
    else if (i < n0 + n1 + n2) { s = s2; h = h2; l = l2; idx = i - n0 - n1; }
    else                       { s = s3; h = h3; l = l3; idx = i - n0 - n1 - n2; }

    float4 v = reinterpret_cast<const float4*>(s)[idx];
    __nv_bfloat162 ha, hb, la, lb;
    ha.x = __float2bfloat16(v.x); ha.y = __float2bfloat16(v.y);
    hb.x = __float2bfloat16(v.z); hb.y = __float2bfloat16(v.w);
    la.x = __float2bfloat16(v.x - __bfloat162float(ha.x));
    la.y = __float2bfloat16(v.y - __bfloat162float(ha.y));
    lb.x = __float2bfloat16(v.z - __bfloat162float(hb.x));
    lb.y = __float2bfloat16(v.w - __bfloat162float(hb.y));
    reinterpret_cast<__nv_bfloat162*>(h)[2 * idx]     = ha;
    reinterpret_cast<__nv_bfloat162*>(h)[2 * idx + 1] = hb;
    reinterpret_cast<__nv_bfloat162*>(l)[2 * idx]     = la;
    reinterpret_cast<__nv_bfloat162*>(l)[2 * idx + 1] = lb;

    if (is_phr) {
        const size_t row = (size_t)idx >> 7;
        const int col = (idx & 127) << 2;
        *reinterpret_cast<float4*>(&out_sem[row * (QS + FS) + col]) = v;
    }
}

// ---------------------------------------------------------------------------
// Tensor-core NT GEMM, 128x64 block tile (R8 proven shape), cp.async 3-stage,
// B fragments via ldsm_x4. Transposed epilogue CT[b][n][m_local].
// 8 warps 4x2, warp tile 32x32, 2 CTAs/SM.
// ---------------------------------------------------------------------------
#define APITCH 40
#define KC 32
#define GSTAGE (384 * APITCH)   // Ah(128) Al(128) Bh(64) Bl(64) rows per stage

__device__ __forceinline__ void gemm_issue_stage(
    __nv_bfloat16* smem, int st, int tid, int m0, int n0, int k0, int K,
    const __nv_bfloat16* Ahi, const __nv_bfloat16* Alo,
    const __nv_bfloat16* Bhi, const __nv_bfloat16* Blo)
{
    __nv_bfloat16* base = smem + st * GSTAGE;
#pragma unroll
    for (int e = 0; e < 2; e++) {
        int idx = tid + e * 256;
        int row = idx >> 2, c = (idx & 3) * 8;
        cpasync16(&base[row * APITCH + c], &Ahi[(size_t)(m0 + row) * K + k0 + c]);
        cpasync16(&base[128 * APITCH + row * APITCH + c],
                  &Alo[(size_t)(m0 + row) * K + k0 + c]);
    }
    {
        int row = tid >> 2, c = (tid & 3) * 8;
        cpasync16(&base[256 * APITCH + row * APITCH + c],
                  &Bhi[(size_t)(n0 + row) * K + k0 + c]);
        cpasync16(&base[320 * APITCH + row * APITCH + c],
                  &Blo[(size_t)(n0 + row) * K + k0 + c]);
    }
    asm volatile("cp.async.commit_group;");
}

__device__ __forceinline__ void gemm_body_T(
    __nv_bfloat16* gsm,
    const __nv_bfloat16* __restrict__ Ahi, const __nv_bfloat16* __restrict__ Alo,
    const __nv_bfloat16* __restrict__ Bhi, const __nv_bfloat16* __restrict__ Blo,
    const float* __restrict__ bias, float* __restrict__ CT,
    int K, int bshift, int m0, int n0)
{
    const int tid = threadIdx.x;
    const int lane = tid & 31;
    const int wid = tid >> 5;
    const int wm = wid >> 1;
    const int wn = wid & 1;
    const int width = 1 << bshift;
    const int wmask = width - 1;

    const int lq = lane >> 3;
    const int lr = lane & 7;

    float acc[2][4][4];
#pragma unroll
    for (int i = 0; i < 2; i++)
#pragma unroll
        for (int j = 0; j < 4; j++)
#pragma unroll
            for (int r = 0; r < 4; r++) acc[i][j][r] = 0.0f;

    const int NC = K / KC;
    gemm_issue_stage(gsm, 0, tid, m0, n0, 0, K, Ahi, Alo, Bhi, Blo);
    gemm_issue_stage(gsm, 1, tid, m0, n0, KC, K, Ahi, Alo, Bhi, Blo);

    int buf = 0;
    for (int c = 0; c < NC; c++) {
        if (c + 2 < NC) {
            gemm_issue_stage(gsm, (c + 2) % 3, tid, m0, n0, (c + 2) * KC, K,
                             Ahi, Alo, Bhi, Blo);
            asm volatile("cp.async.wait_group 2;" ::: "memory");
        } else if (c + 1 < NC) {
            asm volatile("cp.async.wait_group 1;" ::: "memory");
        } else {
            asm volatile("cp.async.wait_group 0;" ::: "memory");
        }
        __syncthreads();

        const __nv_bfloat16* Ah_s = gsm + buf * GSTAGE;
        const __nv_bfloat16* Al_s = Ah_s + 128 * APITCH;
        const __nv_bfloat16* Bh_s = Ah_s + 256 * APITCH;
        const __nv_bfloat16* Bl_s = Ah_s + 320 * APITCH;

#pragma unroll
        for (int ks = 0; ks < KC; ks += 16) {
            uint32_t ah[2][4], al[2][4];
#pragma unroll
            for (int ma = 0; ma < 2; ma++) {
                const int m_local = wm * 32 + ma * 16 + (lq & 1) * 8 + lr;
                const int k_local = ks + (lq >> 1) * 8;
                ldsm_x4(ah[ma][0], ah[ma][1], ah[ma][2], ah[ma][3],
                        smem_u32(&Ah_s[m_local * APITCH + k_local]));
                ldsm_x4(al[ma][0], al[ma][1], al[ma][2], al[ma][3],
                        smem_u32(&Al_s[m_local * APITCH + k_local]));
            }
            // B: 4 n-groups of 8; one ldsm_x4 covers 2 n-groups x 2 k-halves
            uint32_t bh[4][2], bl[4][2];
#pragma unroll
            for (int nb = 0; nb < 2; nb++) {
                const int n_local = wn * 32 + nb * 16 + (lq >> 1) * 8 + lr;
                const int k_local = ks + (lq & 1) * 8;
                uint32_t r0, r1, r2, r3;
                ldsm_x4(r0, r1, r2, r3,
                        smem_u32(&Bh_s[n_local * APITCH + k_local]));
                bh[2 * nb][0] = r0; bh[2 * nb][1] = r1;
                bh[2 * nb + 1][0] = r2; bh[2 * nb + 1][1] = r3;
                ldsm_x4(r0, r1, r2, r3,
                        smem_u32(&Bl_s[n_local * APITCH + k_local]));
                bl[2 * nb][0] = r0; bl[2 * nb][1] = r1;
                bl[2 * nb + 1][0] = r2; bl[2 * nb + 1][1] = r3;
            }
#pragma unroll
            for (int ma = 0; ma < 2; ma++)
#pragma unroll
                for (int na = 0; na < 4; na++) {
                    mma_bf16(acc[ma][na], ah[ma], bh[na]);
                    mma_bf16(acc[ma][na], ah[ma], bl[na]);
                    mma_bf16(acc[ma][na], al[ma], bh[na]);
                }
        }
        __syncthreads();
        buf = (buf + 1) % 3;
    }

    const int er = lane >> 2;
    const int ec = (lane & 3) << 1;
#pragma unroll
    for (int ma = 0; ma < 2; ma++) {
        const int mbase = m0 + wm * 32 + ma * 16;
#pragma unroll
        for (int na = 0; na < 4; na++) {
            const int nbase = n0 + wn * 32 + na * 8 + ec;
            float b0 = 0.0f, b1 = 0.0f;
            if (bias) { b0 = bias[nbase]; b1 = bias[nbase + 1]; }
#pragma unroll
            for (int rr = 0; rr < 2; rr++) {
                const int m = mbase + er + 8 * rr;
                const size_t base = ((size_t)(m >> bshift) * BN) * width
                                    + (m & wmask);
                CT[base + (size_t)nbase * width]       = acc[ma][na][2 * rr]     + b0;
                CT[base + (size_t)(nbase + 1) * width] = acc[ma][na][2 * rr + 1] + b1;
            }
        }
    }
}

// One launch, 48 y-tiles: y<32 -> Uv (K=1024, longer, scheduled first),
// y>=32 -> Wh (K=512).
__global__ __launch_bounds__(256, 2) void gemm_dual_T(
    const __nv_bfloat16* __restrict__ A0h, const __nv_bfloat16* __restrict__ A0l,
    const __nv_bfloat16* __restrict__ B0h, const __nv_bfloat16* __restrict__ B0l,
    float* __restrict__ C0T,                        // UvT
    const __nv_bfloat16* __restrict__ A1h, const __nv_bfloat16* __restrict__ A1l,
    const __nv_bfloat16* __restrict__ B1h, const __nv_bfloat16* __restrict__ B1l,
    const float* __restrict__ bias1, float* __restrict__ C1T)  // WhT
{
    extern __shared__ __nv_bfloat16 gsm[];
    if ((int)blockIdx.y < 32) {
        gemm_body_T(gsm, A0h, A0l, B0h, B0l, nullptr, C0T, FS, 7,
                    blockIdx.y * 128, blockIdx.x * 64);
    } else {
        gemm_body_T(gsm, A1h, A1l, B1h, B1l, bias1, C1T, QS, 6,
                    (blockIdx.y - 32) * 128, blockIdx.x * 64);
    }
}

// ---------------------------------------------------------------------------
// Fused energies + softmax, v-split for occupancy.
// Block: 512 threads = 16 warps. warp = (q 0..7, vhalf 0..1); lane owns
// v = vhalf*64 + 2*lane + {0,1}.
// ---------------------------------------------------------------------------
#define QT 8
#define ECH 32
#define NCHUNK (BN / ECH)

__global__ __launch_bounds__(512) void energy_softmax_kernel(
    const float* __restrict__ WhT, const float* __restrict__ UvT,
    const float* __restrict__ w,
    float* __restrict__ energies, float* __restrict__ weights,
    __nv_bfloat16* __restrict__ wt_hi, __nv_bfloat16* __restrict__ wt_lo)
{
    __shared__ alignas(16) float Cs[2][ECH][LV];
    __shared__ alignas(16) float As[2][ECH][QT];
    __shared__ float ws[BN];
    __shared__ alignas(16) float red[QT][LV];

    const int b = blockIdx.y;
    const int q0 = blockIdx.x * QT;
    const int tid = threadIdx.x;
    const int lane = tid & 31;
    const int wid = tid >> 5;
    const int ql = wid >> 1;
    const int vh = wid & 1;
    const int v0 = vh * 64 + 2 * lane;

    const float* AbT = WhT + (size_t)b * BN * LQ;
    const float* CbT = UvT + (size_t)b * BN * LV;

    for (int i = tid; i < BN; i += 512) ws[i] = w[i];

    auto issue = [&](int c) {
        const int buf = c & 1;
        const int n0 = c * ECH;
#pragma unroll
        for (int e = 0; e < 2; e++) {
            const int o = tid + e * 512;
            const int row = o >> 5, col = (o & 31) * 4;
            cpasync16(&Cs[buf][row][col], &CbT[(size_t)(n0 + row) * LV + col]);
        }
        if (tid < 64) {
            const int row = tid >> 1, half = tid & 1;
            cpasync16(&As[buf][row][half * 4],
                      &AbT[(size_t)(n0 + row) * LQ + q0 + half * 4]);
        }
        asm volatile("cp.async.commit_group;");
    };

    float acc0 = 0.0f, acc1 = 0.0f;

    issue(0);
    for (int c = 0; c < NCHUNK; c++) {
        if (c + 1 < NCHUNK) {
            issue(c + 1);
            asm volatile("cp.async.wait_group 1;" ::: "memory");
        } else {
            asm volatile("cp.async.wait_group 0;" ::: "memory");
        }
        __syncthreads();
        const int buf = c & 1;
        const int nb = c * ECH;
#pragma unroll
        for (int kk = 0; kk < ECH; kk++) {
            const float a = As[buf][kk][ql];
            const float wn = ws[nb + kk];
            const float2 cv = *reinterpret_cast<const float2*>(
                &Cs[buf][kk][v0]);
            acc0 += wn * tanh_fast(a + cv.x);
            acc1 += wn * tanh_fast(a + cv.y);
        }
        __syncthreads();
    }

    red[ql][v0] = acc0;
    red[ql][v0 + 1] = acc1;
    __syncthreads();

    if (vh == 0) {
        const float4 a4 = *reinterpret_cast<const float4*>(&red[ql][4 * lane]);
        float acc[4] = {a4.x, a4.y, a4.z, a4.w};

        float mx = fmaxf(fmaxf(acc[0], acc[1]), fmaxf(acc[2], acc[3]));
#pragma unroll
        for (int o = 16; o > 0; o >>= 1)
            mx = fmaxf(mx, __shfl_xor_sync(0xFFFFFFFFu, mx, o));
        float ex[4], s = 0.0f;
#pragma unroll
        for (int j = 0; j < 4; j++) { ex[j] = __expf(acc[j] - mx); s += ex[j]; }
#pragma unroll
        for (int o = 16; o > 0; o >>= 1)
            s += __shfl_xor_sync(0xFFFFFFFFu, s, o);
        const float inv = __fdividef(1.0f, s);

        const size_t row = (size_t)b * LQ + q0 + ql;
        const size_t off = row * LV + 4 * lane;

        float4 e4; e4.x = acc[0]; e4.y = acc[1]; e4.z = acc[2]; e4.w = acc[3];
        *reinterpret_cast<float4*>(&energies[off]) = e4;

        float wv[4];
#pragma unroll
        for (int j = 0; j < 4; j++) wv[j] = ex[j] * inv;
        float4 w4; w4.x = wv[0]; w4.y = wv[1]; w4.z = wv[2]; w4.w = wv[3];
        *reinterpret_cast<float4*>(&weights[off]) = w4;

        __nv_bfloat162 h01, h23, l01, l23;
        h01.x = __float2bfloat16(wv[0]); h01.y = __float2bfloat16(wv[1]);
        h23.x = __float2bfloat16(wv[2]); h23.y = __float2bfloat16(wv[3]);
        l01.x = __float2bfloat16(wv[0] - __bfloat162float(h01.x));
        l01.y = __float2bfloat16(wv[1] - __bfloat162float(h01.y));
        l23.x = __float2bfloat16(wv[2] - __bfloat162float(h23.x));
        l23.y = __float2bfloat16(wv[3] - __bfloat162float(h23.y));
        uint2 hh, ll;
        hh.x = *reinterpret_cast<uint32_t*>(&h01);
        hh.y = *reinterpret_cast<uint32_t*>(&h23);
        ll.x = *reinterpret_cast<uint32_t*>(&l01);
        ll.y = *reinterpret_cast<uint32_t*>(&l23);
        *reinterpret_cast<uint2*>(&wt_hi[off]) = hh;
        *reinterpret_cast<uint2*>(&wt_lo[off]) = ll;
    }
}

// ---------------------------------------------------------------------------
// Tensor-core aligned: out[b,q,QS+f] = sum_v weights[b,q,v] * vis[b,v,f]
// ---------------------------------------------------------------------------
#define WPITCH 136

__global__ __launch_bounds__(256) void aligned_tc_kernel(
    const __nv_bfloat16* __restrict__ wt_hi, const __nv_bfloat16* __restrict__ wt_lo,
    const __nv_bfloat16* __restrict__ vis_hi, const __nv_bfloat16* __restrict__ vis_lo,
    float* __restrict__ out_sem)
{
    extern __shared__ __nv_bfloat16 asm_[];
    __nv_bfloat16* Wh_s = asm_;
    __nv_bfloat16* Wl_s = asm_ + 64 * WPITCH;
    __nv_bfloat16* Vh_s = asm_ + 128 * WPITCH;
    __nv_bfloat16* Vl_s = asm_ + 256 * WPITCH;

    const int b = blockIdx.y;
    const int f0 = blockIdx.x * 128;
    const int tid = threadIdx.x;
    const int lane = tid & 31;
    const int wid = tid >> 5;
    const int wm = wid >> 2;
    const int wn = wid & 3;
    const int lq = lane >> 3;
    const int lr = lane & 7;

#pragma unroll
    for (int e = 0; e < 4; e++) {
        int idx = tid + e * 256;
        int row = idx >> 4, c = (idx & 15) * 8;
        cpasync16(&Wh_s[row * WPITCH + c], &wt_hi[((size_t)b * LQ + row) * LV + c]);
        cpasync16(&Wl_s[row * WPITCH + c], &wt_lo[((size_t)b * LQ + row) * LV + c]);
    }
#pragma unroll
    for (int e = 0; e < 8; e++) {
        int idx = tid + e * 256;
        int row = idx >> 4, c = (idx & 15) * 8;
        cpasync16(&Vh_s[row * WPITCH + c],
                  &vis_hi[((size_t)b * LV + row) * FS + f0 + c]);
        cpasync16(&Vl_s[row * WPITCH + c],
                  &vis_lo[((size_t)b * LV + row) * FS + f0 + c]);
    }
    asm volatile("cp.async.commit_group;");
    asm volatile("cp.async.wait_group 0;" ::: "memory");
    __syncthreads();

    float acc[2][4][4];
#pragma unroll
    for (int i = 0; i < 2; i++)
#pragma unroll
        for (int j = 0; j < 4; j++)
#pragma unroll
            for (int r = 0; r < 4; r++) acc[i][j][r] = 0.0f;

#pragma unroll
    for (int ks = 0; ks < 8; ks++) {
        uint32_t ah[2][4], al[2][4];
#pragma unroll
        for (int ma = 0; ma < 2; ma++) {
            const int m_local = wm * 32 + ma * 16 + (lq & 1) * 8 + lr;
            const int k_local = ks * 16 + (lq >> 1) * 8;
            ldsm_x4(ah[ma][0], ah[ma][1], ah[ma][2], ah[ma][3],
                    smem_u32(&Wh_s[m_local * WPITCH + k_local]));
            ldsm_x4(al[ma][0], al[ma][1], al[ma][2], al[ma][3],
                    smem_u32(&Wl_s[m_local * WPITCH + k_local]));
        }
        uint32_t bh[4][2], bl[4][2];
#pragma unroll
        for (int np = 0; np < 2; np++) {
            const int krow = ks * 16 + (lq & 1) * 8 + lr;
            const int ncol = wn * 32 + np * 16 + (lq >> 1) * 8;
            uint32_t r0, r1, r2, r3;
            ldsm_x4_t(r0, r1, r2, r3, smem_u32(&Vh_s[krow * WPITCH + ncol]));
            bh[np * 2][0] = r0; bh[np * 2][1] = r1;
            bh[np * 2 + 1][0] = r2; bh[np * 2 + 1][1] = r3;
            ldsm_x4_t(r0, r1, r2, r3, smem_u32(&Vl_s[krow * WPITCH + ncol]));
            bl[np * 2][0] = r0; bl[np * 2][1] = r1;
            bl[np * 2 + 1][0] = r2; bl[np * 2 + 1][1] = r3;
        }
#pragma unroll
        for (int ma = 0; ma < 2; ma++)
#pragma unroll
            for (int na = 0; na < 4; na++) {
                mma_bf16(acc[ma][na], ah[ma], bh[na]);
                mma_bf16(acc[ma][na], ah[ma], bl[na]);
                mma_bf16(acc[ma][na], al[ma], bh[na]);
            }
    }

    const int er = lane >> 2;
    const int ec = (lane & 3) << 1;
#pragma unroll
    for (int ma = 0; ma < 2; ma++) {
        const int qbase = wm * 32 + ma * 16;
#pragma unroll
        for (int na = 0; na < 4; na++) {
            const int f = f0 + wn * 32 + na * 8 + ec;
            float2 v0, v1;
            v0.x = acc[ma][na][0]; v0.y = acc[ma][na][1];
            v1.x = acc[ma][na][2]; v1.y = acc[ma][na][3];
            *reinterpret_cast<float2*>(
                &out_sem[((size_t)b * LQ + qbase + er) * (QS + FS) + QS + f]) = v0;
            *reinterpret_cast<float2*>(
                &out_sem[((size_t)b * LQ + qbase + er + 8) * (QS + FS) + QS + f]) = v1;
        }
    }
}

extern "C" void kernel_launch(void* const* d_in, const int* in_sizes, int n_in,
                              void* d_out, int out_size)
{
    const float* phr  = (const float*)d_in[0];
    const float* vis  = (const float*)d_in[1];
    const float* W    = (const float*)d_in[2];
    const float* U    = (const float*)d_in[3];
    const float* bias = (const float*)d_in[4];
    const float* w    = (const float*)d_in[5];

    float* out = (float*)d_out;
    float* out_sem = out;
    float* out_w   = out + (size_t)NB * LQ * (QS + FS);
    float* out_e   = out_w + (size_t)NB * LQ * LV;

    float *WhT, *UvT;
    __nv_bfloat16 *phr_hi, *phr_lo, *vis_hi, *vis_lo, *W_hi, *W_lo, *U_hi, *U_lo;
    __nv_bfloat16 *wt_hi, *wt_lo;
    cudaGetSymbolAddress((void**)&WhT, g_WhT);
    cudaGetSymbolAddress((void**)&UvT, g_UvT);
    cudaGetSymbolAddress((void**)&phr_hi, g_phr_hi);
    cudaGetSymbolAddress((void**)&phr_lo, g_phr_lo);
    cudaGetSymbolAddress((void**)&vis_hi, g_vis_hi);
    cudaGetSymbolAddress((void**)&vis_lo, g_vis_lo);
    cudaGetSymbolAddress((void**)&W_hi, g_W_hi);
    cudaGetSymbolAddress((void**)&W_lo, g_W_lo);
    cudaGetSymbolAddress((void**)&U_hi, g_U_hi);
    cudaGetSymbolAddress((void**)&U_lo, g_U_lo);
    cudaGetSymbolAddress((void**)&wt_hi, g_wt_hi);
    cudaGetSymbolAddress((void**)&wt_lo, g_wt_lo);

    cudaFuncSetAttribute(gemm_dual_T,
                         cudaFuncAttributeMaxDynamicSharedMemorySize, 92160);
    cudaFuncSetAttribute(aligned_tc_kernel,
                         cudaFuncAttributeMaxDynamicSharedMemorySize, 104448);

    // split (+ phr concat copy)
    split4_kernel<<<5888, 256>>>(phr, phr_hi, phr_lo, 262144,
                                 vis, vis_hi, vis_lo, 1048576,
                                 W,   W_hi,   W_lo,   65536,
                                 U,   U_hi,   U_lo,   131072,
                                 out_sem);

    // Both GEMMs, one launch, 128x64 tiles, 3-stage pipeline
    // (Uv: y 0..31, K=1024; Wh: y 32..47, K=512; x: 8 n-tiles)
    gemm_dual_T<<<dim3(BN / 64, 48), 256, 92160>>>(
        vis_hi, vis_lo, U_hi, U_lo, UvT,
        phr_hi, phr_lo, W_hi, W_lo, bias, WhT);

    // energies + softmax (v-split, 512 threads)
    energy_softmax_kernel<<<dim3(LQ / QT, NB), 512>>>(WhT, UvT, w, out_e, out_w,
                                                      wt_hi, wt_lo);
    // aligned via tensor cores
    aligned_tc_kernel<<<dim3(FS / 128, NB), 256, 104448>>>(wt_hi, wt_lo,
                                                           vis_hi, vis_lo,
                                                           out_sem);
}

// round 12
// speedup vs baseline: 1.1344x; 1.0540x over previous
#include <cuda_runtime.h>
#include <cuda_bf16.h>
#include <cstdint>
#include <cstddef>

#define NB 32
#define LQ 64
#define LV 128
#define QS 512
#define FS 1024
#define BN 512

// ---------------- scratch (device globals — no allocation) ----------------
// Wh/Uv stored TRANSPOSED per batch: WhT[b][n][q], UvT[b][n][v]
__device__ float g_WhT[(size_t)NB * BN * LQ];
__device__ float g_UvT[(size_t)NB * BN * LV];
__device__ __nv_bfloat16 g_phr_hi[(size_t)NB * LQ * QS];
__device__ __nv_bfloat16 g_phr_lo[(size_t)NB * LQ * QS];
__device__ __nv_bfloat16 g_vis_hi[(size_t)NB * LV * FS];
__device__ __nv_bfloat16 g_vis_lo[(size_t)NB * LV * FS];
__device__ __nv_bfloat16 g_W_hi[(size_t)BN * QS];
__device__ __nv_bfloat16 g_W_lo[(size_t)BN * QS];
__device__ __nv_bfloat16 g_U_hi[(size_t)BN * FS];
__device__ __nv_bfloat16 g_U_lo[(size_t)BN * FS];
__device__ __nv_bfloat16 g_wt_hi[(size_t)NB * LQ * LV];
__device__ __nv_bfloat16 g_wt_lo[(size_t)NB * LQ * LV];

// ---------------------------------------------------------------------------
// Helpers
// ---------------------------------------------------------------------------
__device__ __forceinline__ uint32_t smem_u32(const void* p) {
    return (uint32_t)__cvta_generic_to_shared(p);
}

__device__ __forceinline__ void cpasync16(void* s, const void* g) {
    asm volatile("cp.async.cg.shared.global [%0], [%1], 16;"
                 :: "r"(smem_u32(s)), "l"(g));
}

__device__ __forceinline__ void ldsm_x4(uint32_t& r0, uint32_t& r1,
                                        uint32_t& r2, uint32_t& r3, uint32_t addr) {
    asm volatile("ldmatrix.sync.aligned.m8n8.x4.shared.b16 {%0,%1,%2,%3}, [%4];"
                 : "=r"(r0), "=r"(r1), "=r"(r2), "=r"(r3) : "r"(addr));
}

__device__ __forceinline__ void ldsm_x4_t(uint32_t& r0, uint32_t& r1,
                                          uint32_t& r2, uint32_t& r3, uint32_t addr) {
    asm volatile("ldmatrix.sync.aligned.m8n8.x4.trans.shared.b16 {%0,%1,%2,%3}, [%4];"
                 : "=r"(r0), "=r"(r1), "=r"(r2), "=r"(r3) : "r"(addr));
}

__device__ __forceinline__ void mma_bf16(float* d, const uint32_t* a, const uint32_t* b) {
    asm volatile(
        "mma.sync.aligned.m16n8k16.row.col.f32.bf16.bf16.f32 "
        "{%0,%1,%2,%3}, {%4,%5,%6,%7}, {%8,%9}, {%0,%1,%2,%3};"
        : "+f"(d[0]), "+f"(d[1]), "+f"(d[2]), "+f"(d[3])
        : "r"(a[0]), "r"(a[1]), "r"(a[2]), "r"(a[3]), "r"(b[0]), "r"(b[1]));
}

// Hardware tanh: 1 MUFU op, rel err ~2^-11 (validated: net rel_err 5e-6)
__device__ __forceinline__ float tanh_fast(float x) {
    float y;
    asm("tanh.approx.f32 %0, %1;" : "=f"(y) : "f"(x));
    return y;
}

// ---------------------------------------------------------------------------
// Split pass: fp32 -> (hi, lo) bf16 for 4 arrays; also copies phr into the
// concat output columns [0, QS).
// ---------------------------------------------------------------------------
__global__ __launch_bounds__(256) void split4_kernel(
    const float* __restrict__ s0, __nv_bfloat16* __restrict__ h0, __nv_bfloat16* __restrict__ l0, int n0,
    const float* __restrict__ s1, __nv_bfloat16* __restrict__ h1, __nv_bfloat16* __restrict__ l1, int n1,
    const float* __restrict__ s2, __nv_bfloat16* __restrict__ h2, __nv_bfloat16* __restrict__ l2, int n2,
    const float* __restrict__ s3, __nv_bfloat16* __restrict__ h3, __nv_bfloat16* __restrict__ l3, int n3,
    float* __restrict__ out_sem)
{
    int i = blockIdx.x * 256 + threadIdx.x;
    const float* s; __nv_bfloat16 *h, *l; int idx;
    bool is_phr = false;
    if (i < n0)                { s = s0; h = h0; l = l0; idx = i; is_phr = true; }
    else if (i < n0 + n1)      { s = s1; h = h1; l = l1; idx = i - n0; }
    else if (i < n0 + n1 + n2) { s = s2; h = h2; l = l2; idx = i - n0 - n1; }
    else                       { s = s3; h = h3; l = l3; idx = i - n0 - n1 - n2; }

    float4 v = reinterpret_cast<const float4*>(s)[idx];
    __nv_bfloat162 ha, hb, la, lb;
    ha.x = __float2bfloat16(v.x); ha.y = __float2bfloat16(v.y);
    hb.x = __float2bfloat16(v.z); hb.y = __float2bfloat16(v.w);
    la.x = __float2bfloat16(v.x - __bfloat162float(ha.x));
    la.y = __float2bfloat16(v.y - __bfloat162float(ha.y));
    lb.x = __float2bfloat16(v.z - __bfloat162float(hb.x));
    lb.y = __float2bfloat16(v.w - __bfloat162float(hb.y));
    reinterpret_cast<__nv_bfloat162*>(h)[2 * idx]     = ha;
    reinterpret_cast<__nv_bfloat162*>(h)[2 * idx + 1] = hb;
    reinterpret_cast<__nv_bfloat162*>(l)[2 * idx]     = la;
    reinterpret_cast<__nv_bfloat162*>(l)[2 * idx + 1] = lb;

    if (is_phr) {
        const size_t row = (size_t)idx >> 7;
        const int col = (idx & 127) << 2;
        *reinterpret_cast<float4*>(&out_sem[row * (QS + FS) + col]) = v;
    }
}

// ---------------------------------------------------------------------------
// Tensor-core NT GEMM, 128x64 block tile, KC=64 chunks, cp.async 2-stage,
// B fragments via ldsm_x4. Transposed epilogue CT[b][n][m_local].
// 8 warps 4x2, warp tile 32x32.
// ---------------------------------------------------------------------------
#define APITCH 72               // 64 k + 8 pad halves (144 B rows, 16B-aligned)
#define KC 64
#define GSTAGE (384 * APITCH)   // Ah(128) Al(128) Bh(64) Bl(64) rows per stage

__device__ __forceinline__ void gemm_issue_stage(
    __nv_bfloat16* smem, int st, int tid, int m0, int n0, int k0, int K,
    const __nv_bfloat16* Ahi, const __nv_bfloat16* Alo,
    const __nv_bfloat16* Bhi, const __nv_bfloat16* Blo)
{
    __nv_bfloat16* base = smem + st * GSTAGE;
    // A: 128 rows x 64 k = 1024 cp16 chunks each (hi, lo)
#pragma unroll
    for (int e = 0; e < 4; e++) {
        int idx = tid + e * 256;
        int row = idx >> 3, c = (idx & 7) * 8;
        cpasync16(&base[row * APITCH + c], &Ahi[(size_t)(m0 + row) * K + k0 + c]);
        cpasync16(&base[128 * APITCH + row * APITCH + c],
                  &Alo[(size_t)(m0 + row) * K + k0 + c]);
    }
    // B: 64 rows x 64 k = 512 cp16 chunks each (hi, lo)
#pragma unroll
    for (int e = 0; e < 2; e++) {
        int idx = tid + e * 256;
        int row = idx >> 3, c = (idx & 7) * 8;
        cpasync16(&base[256 * APITCH + row * APITCH + c],
                  &Bhi[(size_t)(n0 + row) * K + k0 + c]);
        cpasync16(&base[320 * APITCH + row * APITCH + c],
                  &Blo[(size_t)(n0 + row) * K + k0 + c]);
    }
    asm volatile("cp.async.commit_group;");
}

__device__ __forceinline__ void gemm_body_T(
    __nv_bfloat16* gsm,
    const __nv_bfloat16* __restrict__ Ahi, const __nv_bfloat16* __restrict__ Alo,
    const __nv_bfloat16* __restrict__ Bhi, const __nv_bfloat16* __restrict__ Blo,
    const float* __restrict__ bias, float* __restrict__ CT,
    int K, int bshift, int m0, int n0)
{
    const int tid = threadIdx.x;
    const int lane = tid & 31;
    const int wid = tid >> 5;
    const int wm = wid >> 1;
    const int wn = wid & 1;
    const int width = 1 << bshift;
    const int wmask = width - 1;

    const int lq = lane >> 3;
    const int lr = lane & 7;

    float acc[2][4][4];
#pragma unroll
    for (int i = 0; i < 2; i++)
#pragma unroll
        for (int j = 0; j < 4; j++)
#pragma unroll
            for (int r = 0; r < 4; r++) acc[i][j][r] = 0.0f;

    const int NC = K / KC;
    gemm_issue_stage(gsm, 0, tid, m0, n0, 0, K, Ahi, Alo, Bhi, Blo);

    for (int c = 0; c < NC; c++) {
        const int st = c & 1;
        if (c + 1 < NC) {
            gemm_issue_stage(gsm, st ^ 1, tid, m0, n0, (c + 1) * KC, K,
                             Ahi, Alo, Bhi, Blo);
            asm volatile("cp.async.wait_group 1;" ::: "memory");
        } else {
            asm volatile("cp.async.wait_group 0;" ::: "memory");
        }
        __syncthreads();

        const __nv_bfloat16* Ah_s = gsm + st * GSTAGE;
        const __nv_bfloat16* Al_s = Ah_s + 128 * APITCH;
        const __nv_bfloat16* Bh_s = Ah_s + 256 * APITCH;
        const __nv_bfloat16* Bl_s = Ah_s + 320 * APITCH;

#pragma unroll
        for (int ks = 0; ks < KC; ks += 16) {
            uint32_t ah[2][4], al[2][4];
#pragma unroll
            for (int ma = 0; ma < 2; ma++) {
                const int m_local = wm * 32 + ma * 16 + (lq & 1) * 8 + lr;
                const int k_local = ks + (lq >> 1) * 8;
                ldsm_x4(ah[ma][0], ah[ma][1], ah[ma][2], ah[ma][3],
                        smem_u32(&Ah_s[m_local * APITCH + k_local]));
                ldsm_x4(al[ma][0], al[ma][1], al[ma][2], al[ma][3],
                        smem_u32(&Al_s[m_local * APITCH + k_local]));
            }
            // B: 4 n-groups of 8; one ldsm_x4 covers 2 n-groups x 2 k-halves
            uint32_t bh[4][2], bl[4][2];
#pragma unroll
            for (int nb = 0; nb < 2; nb++) {
                const int n_local = wn * 32 + nb * 16 + (lq >> 1) * 8 + lr;
                const int k_local = ks + (lq & 1) * 8;
                uint32_t r0, r1, r2, r3;
                ldsm_x4(r0, r1, r2, r3,
                        smem_u32(&Bh_s[n_local * APITCH + k_local]));
                bh[2 * nb][0] = r0; bh[2 * nb][1] = r1;
                bh[2 * nb + 1][0] = r2; bh[2 * nb + 1][1] = r3;
                ldsm_x4(r0, r1, r2, r3,
                        smem_u32(&Bl_s[n_local * APITCH + k_local]));
                bl[2 * nb][0] = r0; bl[2 * nb][1] = r1;
                bl[2 * nb + 1][0] = r2; bl[2 * nb + 1][1] = r3;
            }
#pragma unroll
            for (int ma = 0; ma < 2; ma++)
#pragma unroll
                for (int na = 0; na < 4; na++) {
                    mma_bf16(acc[ma][na], ah[ma], bh[na]);
                    mma_bf16(acc[ma][na], ah[ma], bl[na]);
                    mma_bf16(acc[ma][na], al[ma], bh[na]);
                }
        }
        __syncthreads();
    }

    const int er = lane >> 2;
    const int ec = (lane & 3) << 1;
#pragma unroll
    for (int ma = 0; ma < 2; ma++) {
        const int mbase = m0 + wm * 32 + ma * 16;
#pragma unroll
        for (int na = 0; na < 4; na++) {
            const int nbase = n0 + wn * 32 + na * 8 + ec;
            float b0 = 0.0f, b1 = 0.0f;
            if (bias) { b0 = bias[nbase]; b1 = bias[nbase + 1]; }
#pragma unroll
            for (int rr = 0; rr < 2; rr++) {
                const int m = mbase + er + 8 * rr;
                const size_t base = ((size_t)(m >> bshift) * BN) * width
                                    + (m & wmask);
                CT[base + (size_t)nbase * width]       = acc[ma][na][2 * rr]     + b0;
                CT[base + (size_t)(nbase + 1) * width] = acc[ma][na][2 * rr + 1] + b1;
            }
        }
    }
}

// One launch, 48 y-tiles: y<32 -> Uv (K=1024, longer, scheduled first),
// y>=32 -> Wh (K=512).
__global__ __launch_bounds__(256) void gemm_dual_T(
    const __nv_bfloat16* __restrict__ A0h, const __nv_bfloat16* __restrict__ A0l,
    const __nv_bfloat16* __restrict__ B0h, const __nv_bfloat16* __restrict__ B0l,
    float* __restrict__ C0T,                        // UvT
    const __nv_bfloat16* __restrict__ A1h, const __nv_bfloat16* __restrict__ A1l,
    const __nv_bfloat16* __restrict__ B1h, const __nv_bfloat16* __restrict__ B1l,
    const float* __restrict__ bias1, float* __restrict__ C1T)  // WhT
{
    extern __shared__ __nv_bfloat16 gsm[];
    if ((int)blockIdx.y < 32) {
        gemm_body_T(gsm, A0h, A0l, B0h, B0l, nullptr, C0T, FS, 7,
                    blockIdx.y * 128, blockIdx.x * 64);
    } else {
        gemm_body_T(gsm, A1h, A1l, B1h, B1l, bias1, C1T, QS, 6,
                    (blockIdx.y - 32) * 128, blockIdx.x * 64);
    }
}

// ---------------------------------------------------------------------------
// Fused energies + softmax, v-split for occupancy (R8, proven).
// Block: 512 threads = 16 warps. warp = (q 0..7, vhalf 0..1); lane owns
// v = vhalf*64 + 2*lane + {0,1}.
// ---------------------------------------------------------------------------
#define QT 8
#define ECH 32
#define NCHUNK (BN / ECH)

__global__ __launch_bounds__(512) void energy_softmax_kernel(
    const float* __restrict__ WhT, const float* __restrict__ UvT,
    const float* __restrict__ w,
    float* __restrict__ energies, float* __restrict__ weights,
    __nv_bfloat16* __restrict__ wt_hi, __nv_bfloat16* __restrict__ wt_lo)
{
    __shared__ alignas(16) float Cs[2][ECH][LV];
    __shared__ alignas(16) float As[2][ECH][QT];
    __shared__ float ws[BN];
    __shared__ alignas(16) float red[QT][LV];

    const int b = blockIdx.y;
    const int q0 = blockIdx.x * QT;
    const int tid = threadIdx.x;
    const int lane = tid & 31;
    const int wid = tid >> 5;
    const int ql = wid >> 1;
    const int vh = wid & 1;
    const int v0 = vh * 64 + 2 * lane;

    const float* AbT = WhT + (size_t)b * BN * LQ;
    const float* CbT = UvT + (size_t)b * BN * LV;

    for (int i = tid; i < BN; i += 512) ws[i] = w[i];

    auto issue = [&](int c) {
        const int buf = c & 1;
        const int n0 = c * ECH;
#pragma unroll
        for (int e = 0; e < 2; e++) {
            const int o = tid + e * 512;
            const int row = o >> 5, col = (o & 31) * 4;
            cpasync16(&Cs[buf][row][col], &CbT[(size_t)(n0 + row) * LV + col]);
        }
        if (tid < 64) {
            const int row = tid >> 1, half = tid & 1;
            cpasync16(&As[buf][row][half * 4],
                      &AbT[(size_t)(n0 + row) * LQ + q0 + half * 4]);
        }
        asm volatile("cp.async.commit_group;");
    };

    float acc0 = 0.0f, acc1 = 0.0f;

    issue(0);
    for (int c = 0; c < NCHUNK; c++) {
        if (c + 1 < NCHUNK) {
            issue(c + 1);
            asm volatile("cp.async.wait_group 1;" ::: "memory");
        } else {
            asm volatile("cp.async.wait_group 0;" ::: "memory");
        }
        __syncthreads();
        const int buf = c & 1;
        const int nb = c * ECH;
#pragma unroll
        for (int kk = 0; kk < ECH; kk++) {
            const float a = As[buf][kk][ql];
            const float wn = ws[nb + kk];
            const float2 cv = *reinterpret_cast<const float2*>(
                &Cs[buf][kk][v0]);
            acc0 += wn * tanh_fast(a + cv.x);
            acc1 += wn * tanh_fast(a + cv.y);
        }
        __syncthreads();
    }

    red[ql][v0] = acc0;
    red[ql][v0 + 1] = acc1;
    __syncthreads();

    if (vh == 0) {
        const float4 a4 = *reinterpret_cast<const float4*>(&red[ql][4 * lane]);
        float acc[4] = {a4.x, a4.y, a4.z, a4.w};

        float mx = fmaxf(fmaxf(acc[0], acc[1]), fmaxf(acc[2], acc[3]));
#pragma unroll
        for (int o = 16; o > 0; o >>= 1)
            mx = fmaxf(mx, __shfl_xor_sync(0xFFFFFFFFu, mx, o));
        float ex[4], s = 0.0f;
#pragma unroll
        for (int j = 0; j < 4; j++) { ex[j] = __expf(acc[j] - mx); s += ex[j]; }
#pragma unroll
        for (int o = 16; o > 0; o >>= 1)
            s += __shfl_xor_sync(0xFFFFFFFFu, s, o);
        const float inv = __fdividef(1.0f, s);

        const size_t row = (size_t)b * LQ + q0 + ql;
        const size_t off = row * LV + 4 * lane;

        float4 e4; e4.x = acc[0]; e4.y = acc[1]; e4.z = acc[2]; e4.w = acc[3];
        *reinterpret_cast<float4*>(&energies[off]) = e4;

        float wv[4];
#pragma unroll
        for (int j = 0; j < 4; j++) wv[j] = ex[j] * inv;
        float4 w4; w4.x = wv[0]; w4.y = wv[1]; w4.z = wv[2]; w4.w = wv[3];
        *reinterpret_cast<float4*>(&weights[off]) = w4;

        __nv_bfloat162 h01, h23, l01, l23;
        h01.x = __float2bfloat16(wv[0]); h01.y = __float2bfloat16(wv[1]);
        h23.x = __float2bfloat16(wv[2]); h23.y = __float2bfloat16(wv[3]);
        l01.x = __float2bfloat16(wv[0] - __bfloat162float(h01.x));
        l01.y = __float2bfloat16(wv[1] - __bfloat162float(h01.y));
        l23.x = __float2bfloat16(wv[2] - __bfloat162float(h23.x));
        l23.y = __float2bfloat16(wv[3] - __bfloat162float(h23.y));
        uint2 hh, ll;
        hh.x = *reinterpret_cast<uint32_t*>(&h01);
        hh.y = *reinterpret_cast<uint32_t*>(&h23);
        ll.x = *reinterpret_cast<uint32_t*>(&l01);
        ll.y = *reinterpret_cast<uint32_t*>(&l23);
        *reinterpret_cast<uint2*>(&wt_hi[off]) = hh;
        *reinterpret_cast<uint2*>(&wt_lo[off]) = ll;
    }
}

// ---------------------------------------------------------------------------
// Tensor-core aligned: out[b,q,QS+f] = sum_v weights[b,q,v] * vis[b,v,f]
// ---------------------------------------------------------------------------
#define WPITCH 136

__global__ __launch_bounds__(256) void aligned_tc_kernel(
    const __nv_bfloat16* __restrict__ wt_hi, const __nv_bfloat16* __restrict__ wt_lo,
    const __nv_bfloat16* __restrict__ vis_hi, const __nv_bfloat16* __restrict__ vis_lo,
    float* __restrict__ out_sem)
{
    extern __shared__ __nv_bfloat16 asm_[];
    __nv_bfloat16* Wh_s = asm_;
    __nv_bfloat16* Wl_s = asm_ + 64 * WPITCH;
    __nv_bfloat16* Vh_s = asm_ + 128 * WPITCH;
    __nv_bfloat16* Vl_s = asm_ + 256 * WPITCH;

    const int b = blockIdx.y;
    const int f0 = blockIdx.x * 128;
    const int tid = threadIdx.x;
    const int lane = tid & 31;
    const int wid = tid >> 5;
    const int wm = wid >> 2;
    const int wn = wid & 3;
    const int lq = lane >> 3;
    const int lr = lane & 7;

#pragma unroll
    for (int e = 0; e < 4; e++) {
        int idx = tid + e * 256;
        int row = idx >> 4, c = (idx & 15) * 8;
        cpasync16(&Wh_s[row * WPITCH + c], &wt_hi[((size_t)b * LQ + row) * LV + c]);
        cpasync16(&Wl_s[row * WPITCH + c], &wt_lo[((size_t)b * LQ + row) * LV + c]);
    }
#pragma unroll
    for (int e = 0; e < 8; e++) {
        int idx = tid + e * 256;
        int row = idx >> 4, c = (idx & 15) * 8;
        cpasync16(&Vh_s[row * WPITCH + c],
                  &vis_hi[((size_t)b * LV + row) * FS + f0 + c]);
        cpasync16(&Vl_s[row * WPITCH + c],
                  &vis_lo[((size_t)b * LV + row) * FS + f0 + c]);
    }
    asm volatile("cp.async.commit_group;");
    asm volatile("cp.async.wait_group 0;" ::: "memory");
    __syncthreads();

    float acc[2][4][4];
#pragma unroll
    for (int i = 0; i < 2; i++)
#pragma unroll
        for (int j = 0; j < 4; j++)
#pragma unroll
            for (int r = 0; r < 4; r++) acc[i][j][r] = 0.0f;

#pragma unroll
    for (int ks = 0; ks < 8; ks++) {
        uint32_t ah[2][4], al[2][4];
#pragma unroll
        for (int ma = 0; ma < 2; ma++) {
            const int m_local = wm * 32 + ma * 16 + (lq & 1) * 8 + lr;
            const int k_local = ks * 16 + (lq >> 1) * 8;
            ldsm_x4(ah[ma][0], ah[ma][1], ah[ma][2], ah[ma][3],
                    smem_u32(&Wh_s[m_local * WPITCH + k_local]));
            ldsm_x4(al[ma][0], al[ma][1], al[ma][2], al[ma][3],
                    smem_u32(&Wl_s[m_local * WPITCH + k_local]));
        }
        uint32_t bh[4][2], bl[4][2];
#pragma unroll
        for (int np = 0; np < 2; np++) {
            const int krow = ks * 16 + (lq & 1) * 8 + lr;
            const int ncol = wn * 32 + np * 16 + (lq >> 1) * 8;
            uint32_t r0, r1, r2, r3;
            ldsm_x4_t(r0, r1, r2, r3, smem_u32(&Vh_s[krow * WPITCH + ncol]));
            bh[np * 2][0] = r0; bh[np * 2][1] = r1;
            bh[np * 2 + 1][0] = r2; bh[np * 2 + 1][1] = r3;
            ldsm_x4_t(r0, r1, r2, r3, smem_u32(&Vl_s[krow * WPITCH + ncol]));
            bl[np * 2][0] = r0; bl[np * 2][1] = r1;
            bl[np * 2 + 1][0] = r2; bl[np * 2 + 1][1] = r3;
        }
#pragma unroll
        for (int ma = 0; ma < 2; ma++)
#pragma unroll
            for (int na = 0; na < 4; na++) {
                mma_bf16(acc[ma][na], ah[ma], bh[na]);
                mma_bf16(acc[ma][na], ah[ma], bl[na]);
                mma_bf16(acc[ma][na], al[ma], bh[na]);
            }
    }

    const int er = lane >> 2;
    const int ec = (lane & 3) << 1;
#pragma unroll
    for (int ma = 0; ma < 2; ma++) {
        const int qbase = wm * 32 + ma * 16;
#pragma unroll
        for (int na = 0; na < 4; na++) {
            const int f = f0 + wn * 32 + na * 8 + ec;
            float2 v0, v1;
            v0.x = acc[ma][na][0]; v0.y = acc[ma][na][1];
            v1.x = acc[ma][na][2]; v1.y = acc[ma][na][3];
            *reinterpret_cast<float2*>(
                &out_sem[((size_t)b * LQ + qbase + er) * (QS + FS) + QS + f]) = v0;
            *reinterpret_cast<float2*>(
                &out_sem[((size_t)b * LQ + qbase + er + 8) * (QS + FS) + QS + f]) = v1;
        }
    }
}

extern "C" void kernel_launch(void* const* d_in, const int* in_sizes, int n_in,
                              void* d_out, int out_size)
{
    const float* phr  = (const float*)d_in[0];
    const float* vis  = (const float*)d_in[1];
    const float* W    = (const float*)d_in[2];
    const float* U    = (const float*)d_in[3];
    const float* bias = (const float*)d_in[4];
    const float* w    = (const float*)d_in[5];

    float* out = (float*)d_out;
    float* out_sem = out;
    float* out_w   = out + (size_t)NB * LQ * (QS + FS);
    float* out_e   = out_w + (size_t)NB * LQ * LV;

    float *WhT, *UvT;
    __nv_bfloat16 *phr_hi, *phr_lo, *vis_hi, *vis_lo, *W_hi, *W_lo, *U_hi, *U_lo;
    __nv_bfloat16 *wt_hi, *wt_lo;
    cudaGetSymbolAddress((void**)&WhT, g_WhT);
    cudaGetSymbolAddress((void**)&UvT, g_UvT);
    cudaGetSymbolAddress((void**)&phr_hi, g_phr_hi);
    cudaGetSymbolAddress((void**)&phr_lo, g_phr_lo);
    cudaGetSymbolAddress((void**)&vis_hi, g_vis_hi);
    cudaGetSymbolAddress((void**)&vis_lo, g_vis_lo);
    cudaGetSymbolAddress((void**)&W_hi, g_W_hi);
    cudaGetSymbolAddress((void**)&W_lo, g_W_lo);
    cudaGetSymbolAddress((void**)&U_hi, g_U_hi);
    cudaGetSymbolAddress((void**)&U_lo, g_U_lo);
    cudaGetSymbolAddress((void**)&wt_hi, g_wt_hi);
    cudaGetSymbolAddress((void**)&wt_lo, g_wt_lo);

    // 2 stages x 384 rows x 72 halves x 2 B = 110,592 B
    cudaFuncSetAttribute(gemm_dual_T,
                         cudaFuncAttributeMaxDynamicSharedMemorySize, 110592);
    cudaFuncSetAttribute(aligned_tc_kernel,
                         cudaFuncAttributeMaxDynamicSharedMemorySize, 104448);

    // split (+ phr concat copy)
    split4_kernel<<<5888, 256>>>(phr, phr_hi, phr_lo, 262144,
                                 vis, vis_hi, vis_lo, 1048576,
                                 W,   W_hi,   W_lo,   65536,
                                 U,   U_hi,   U_lo,   131072,
                                 out_sem);

    // Both GEMMs, one launch, 128x64 tiles, KC=64, 2-stage pipeline
    // (Uv: y 0..31, K=1024; Wh: y 32..47, K=512; x: 8 n-tiles)
    gemm_dual_T<<<dim3(BN / 64, 48), 256, 110592>>>(
        vis_hi, vis_lo, U_hi, U_lo, UvT,
        phr_hi, phr_lo, W_hi, W_lo, bias, WhT);

    // energies + softmax (v-split, 512 threads)
    energy_softmax_kernel<<<dim3(LQ / QT, NB), 512>>>(WhT, UvT, w, out_e, out_w,
                                                      wt_hi, wt_lo);
    // aligned via tensor cores
    aligned_tc_kernel<<<dim3(FS / 128, NB), 256, 104448>>>(wt_hi, wt_lo,
                                                           vis_hi, vis_lo,
                                                           out_sem);
}

// round 13
// speedup vs baseline: 1.1523x; 1.0158x over previous
#include <cuda_runtime.h>
#include <cuda_bf16.h>
#include <cstdint>
#include <cstddef>

#define NB 32
#define LQ 64
#define LV 128
#define QS 512
#define FS 1024
#define BN 512

// ---------------- scratch (device globals — no allocation) ----------------
// Wh/Uv stored TRANSPOSED per batch: WhT[b][n][q], UvT[b][n][v]
__device__ float g_WhT[(size_t)NB * BN * LQ];
__device__ float g_UvT[(size_t)NB * BN * LV];
__device__ __nv_bfloat16 g_phr_hi[(size_t)NB * LQ * QS];
__device__ __nv_bfloat16 g_phr_lo[(size_t)NB * LQ * QS];
__device__ __nv_bfloat16 g_vis_hi[(size_t)NB * LV * FS];
__device__ __nv_bfloat16 g_vis_lo[(size_t)NB * LV * FS];
__device__ __nv_bfloat16 g_W_hi[(size_t)BN * QS];
__device__ __nv_bfloat16 g_W_lo[(size_t)BN * QS];
__device__ __nv_bfloat16 g_U_hi[(size_t)BN * FS];
__device__ __nv_bfloat16 g_U_lo[(size_t)BN * FS];
__device__ __nv_bfloat16 g_wt_hi[(size_t)NB * LQ * LV];
__device__ __nv_bfloat16 g_wt_lo[(size_t)NB * LQ * LV];

// ---------------------------------------------------------------------------
// Helpers
// ---------------------------------------------------------------------------
__device__ __forceinline__ uint32_t smem_u32(const void* p) {
    return (uint32_t)__cvta_generic_to_shared(p);
}

__device__ __forceinline__ void cpasync16(void* s, const void* g) {
    asm volatile("cp.async.cg.shared.global [%0], [%1], 16;"
                 :: "r"(smem_u32(s)), "l"(g));
}

__device__ __forceinline__ void ldsm_x4(uint32_t& r0, uint32_t& r1,
                                        uint32_t& r2, uint32_t& r3, uint32_t addr) {
    asm volatile("ldmatrix.sync.aligned.m8n8.x4.shared.b16 {%0,%1,%2,%3}, [%4];"
                 : "=r"(r0), "=r"(r1), "=r"(r2), "=r"(r3) : "r"(addr));
}

__device__ __forceinline__ void ldsm_x4_t(uint32_t& r0, uint32_t& r1,
                                          uint32_t& r2, uint32_t& r3, uint32_t addr) {
    asm volatile("ldmatrix.sync.aligned.m8n8.x4.trans.shared.b16 {%0,%1,%2,%3}, [%4];"
                 : "=r"(r0), "=r"(r1), "=r"(r2), "=r"(r3) : "r"(addr));
}

__device__ __forceinline__ void mma_bf16(float* d, const uint32_t* a, const uint32_t* b) {
    asm volatile(
        "mma.sync.aligned.m16n8k16.row.col.f32.bf16.bf16.f32 "
        "{%0,%1,%2,%3}, {%4,%5,%6,%7}, {%8,%9}, {%0,%1,%2,%3};"
        : "+f"(d[0]), "+f"(d[1]), "+f"(d[2]), "+f"(d[3])
        : "r"(a[0]), "r"(a[1]), "r"(a[2]), "r"(a[3]), "r"(b[0]), "r"(b[1]));
}

// Hardware tanh: 1 MUFU op, rel err ~2^-11 (validated: net rel_err 5e-6)
__device__ __forceinline__ float tanh_fast(float x) {
    float y;
    asm("tanh.approx.f32 %0, %1;" : "=f"(y) : "f"(x));
    return y;
}

// ---------------------------------------------------------------------------
// Split pass: fp32 -> (hi, lo) bf16 for 4 arrays; also copies phr into the
// concat output columns [0, QS).
// ---------------------------------------------------------------------------
__global__ __launch_bounds__(256) void split4_kernel(
    const float* __restrict__ s0, __nv_bfloat16* __restrict__ h0, __nv_bfloat16* __restrict__ l0, int n0,
    const float* __restrict__ s1, __nv_bfloat16* __restrict__ h1, __nv_bfloat16* __restrict__ l1, int n1,
    const float* __restrict__ s2, __nv_bfloat16* __restrict__ h2, __nv_bfloat16* __restrict__ l2, int n2,
    const float* __restrict__ s3, __nv_bfloat16* __restrict__ h3, __nv_bfloat16* __restrict__ l3, int n3,
    float* __restrict__ out_sem)
{
    int i = blockIdx.x * 256 + threadIdx.x;
    const float* s; __nv_bfloat16 *h, *l; int idx;
    bool is_phr = false;
    if (i < n0)                { s = s0; h = h0; l = l0; idx = i; is_phr = true; }
    else if (i < n0 + n1)      { s = s1; h = h1; l = l1; idx = i - n0; }
    else if (i < n0 + n1 + n2) { s = s2; h = h2; l = l2; idx = i - n0 - n1; }
    else                       { s = s3; h = h3; l = l3; idx = i - n0 - n1 - n2; }

    float4 v = reinterpret_cast<const float4*>(s)[idx];
    __nv_bfloat162 ha, hb, la, lb;
    ha.x = __float2bfloat16(v.x); ha.y = __float2bfloat16(v.y);
    hb.x = __float2bfloat16(v.z); hb.y = __float2bfloat16(v.w);
    la.x = __float2bfloat16(v.x - __bfloat162float(ha.x));
    la.y = __float2bfloat16(v.y - __bfloat162float(ha.y));
    lb.x = __float2bfloat16(v.z - __bfloat162float(hb.x));
    lb.y = __float2bfloat16(v.w - __bfloat162float(hb.y));
    reinterpret_cast<__nv_bfloat162*>(h)[2 * idx]     = ha;
    reinterpret_cast<__nv_bfloat162*>(h)[2 * idx + 1] = hb;
    reinterpret_cast<__nv_bfloat162*>(l)[2 * idx]     = la;
    reinterpret_cast<__nv_bfloat162*>(l)[2 * idx + 1] = lb;

    if (is_phr) {
        const size_t row = (size_t)idx >> 7;
        const int col = (idx & 127) << 2;
        *reinterpret_cast<float4*>(&out_sem[row * (QS + FS) + col]) = v;
    }
}

// ---------------------------------------------------------------------------
// Tensor-core NT GEMM, 128x64 block tile, KC=64 chunks, cp.async 2-stage,
// B fragments via ldsm_x4. Transposed epilogue CT[b][n][m_local], staged
// through smem for coalesced float4 stores.
// 8 warps 4x2, warp tile 32x32.
// ---------------------------------------------------------------------------
#define APITCH 72               // 64 k + 8 pad halves (144 B rows, 16B-aligned)
#define KC 64
#define GSTAGE (384 * APITCH)   // Ah(128) Al(128) Bh(64) Bl(64) rows per stage
#define CPITCH 132              // epilogue staging pitch (floats)

__device__ __forceinline__ void gemm_issue_stage(
    __nv_bfloat16* smem, int st, int tid, int m0, int n0, int k0, int K,
    const __nv_bfloat16* Ahi, const __nv_bfloat16* Alo,
    const __nv_bfloat16* Bhi, const __nv_bfloat16* Blo)
{
    __nv_bfloat16* base = smem + st * GSTAGE;
    // A: 128 rows x 64 k = 1024 cp16 chunks each (hi, lo)
#pragma unroll
    for (int e = 0; e < 4; e++) {
        int idx = tid + e * 256;
        int row = idx >> 3, c = (idx & 7) * 8;
        cpasync16(&base[row * APITCH + c], &Ahi[(size_t)(m0 + row) * K + k0 + c]);
        cpasync16(&base[128 * APITCH + row * APITCH + c],
                  &Alo[(size_t)(m0 + row) * K + k0 + c]);
    }
    // B: 64 rows x 64 k = 512 cp16 chunks each (hi, lo)
#pragma unroll
    for (int e = 0; e < 2; e++) {
        int idx = tid + e * 256;
        int row = idx >> 3, c = (idx & 7) * 8;
        cpasync16(&base[256 * APITCH + row * APITCH + c],
                  &Bhi[(size_t)(n0 + row) * K + k0 + c]);
        cpasync16(&base[320 * APITCH + row * APITCH + c],
                  &Blo[(size_t)(n0 + row) * K + k0 + c]);
    }
    asm volatile("cp.async.commit_group;");
}

__device__ __forceinline__ void gemm_body_T(
    __nv_bfloat16* gsm,
    const __nv_bfloat16* __restrict__ Ahi, const __nv_bfloat16* __restrict__ Alo,
    const __nv_bfloat16* __restrict__ Bhi, const __nv_bfloat16* __restrict__ Blo,
    const float* __restrict__ bias, float* __restrict__ CT,
    int K, int bshift, int m0, int n0)
{
    const int tid = threadIdx.x;
    const int lane = tid & 31;
    const int wid = tid >> 5;
    const int wm = wid >> 1;
    const int wn = wid & 1;
    const int width = 1 << bshift;
    const int wmask = width - 1;

    const int lq = lane >> 3;
    const int lr = lane & 7;

    float acc[2][4][4];
#pragma unroll
    for (int i = 0; i < 2; i++)
#pragma unroll
        for (int j = 0; j < 4; j++)
#pragma unroll
            for (int r = 0; r < 4; r++) acc[i][j][r] = 0.0f;

    const int NC = K / KC;
    gemm_issue_stage(gsm, 0, tid, m0, n0, 0, K, Ahi, Alo, Bhi, Blo);

    for (int c = 0; c < NC; c++) {
        const int st = c & 1;
        if (c + 1 < NC) {
            gemm_issue_stage(gsm, st ^ 1, tid, m0, n0, (c + 1) * KC, K,
                             Ahi, Alo, Bhi, Blo);
            asm volatile("cp.async.wait_group 1;" ::: "memory");
        } else {
            asm volatile("cp.async.wait_group 0;" ::: "memory");
        }
        __syncthreads();

        const __nv_bfloat16* Ah_s = gsm + st * GSTAGE;
        const __nv_bfloat16* Al_s = Ah_s + 128 * APITCH;
        const __nv_bfloat16* Bh_s = Ah_s + 256 * APITCH;
        const __nv_bfloat16* Bl_s = Ah_s + 320 * APITCH;

#pragma unroll
        for (int ks = 0; ks < KC; ks += 16) {
            uint32_t ah[2][4], al[2][4];
#pragma unroll
            for (int ma = 0; ma < 2; ma++) {
                const int m_local = wm * 32 + ma * 16 + (lq & 1) * 8 + lr;
                const int k_local = ks + (lq >> 1) * 8;
                ldsm_x4(ah[ma][0], ah[ma][1], ah[ma][2], ah[ma][3],
                        smem_u32(&Ah_s[m_local * APITCH + k_local]));
                ldsm_x4(al[ma][0], al[ma][1], al[ma][2], al[ma][3],
                        smem_u32(&Al_s[m_local * APITCH + k_local]));
            }
            // B: 4 n-groups of 8; one ldsm_x4 covers 2 n-groups x 2 k-halves
            uint32_t bh[4][2], bl[4][2];
#pragma unroll
            for (int nb = 0; nb < 2; nb++) {
                const int n_local = wn * 32 + nb * 16 + (lq >> 1) * 8 + lr;
                const int k_local = ks + (lq & 1) * 8;
                uint32_t r0, r1, r2, r3;
                ldsm_x4(r0, r1, r2, r3,
                        smem_u32(&Bh_s[n_local * APITCH + k_local]));
                bh[2 * nb][0] = r0; bh[2 * nb][1] = r1;
                bh[2 * nb + 1][0] = r2; bh[2 * nb + 1][1] = r3;
                ldsm_x4(r0, r1, r2, r3,
                        smem_u32(&Bl_s[n_local * APITCH + k_local]));
                bl[2 * nb][0] = r0; bl[2 * nb][1] = r1;
                bl[2 * nb + 1][0] = r2; bl[2 * nb + 1][1] = r3;
            }
#pragma unroll
            for (int ma = 0; ma < 2; ma++)
#pragma unroll
                for (int na = 0; na < 4; na++) {
                    mma_bf16(acc[ma][na], ah[ma], bh[na]);
                    mma_bf16(acc[ma][na], ah[ma], bl[na]);
                    mma_bf16(acc[ma][na], al[ma], bh[na]);
                }
        }
        __syncthreads();
    }

    // --- epilogue: stage C tile [64 n][128 m] in smem, store coalesced ---
    float* cs = reinterpret_cast<float*>(gsm);   // 64 x CPITCH floats (~34 KB)
    const int er = lane >> 2;
    const int ec = (lane & 3) << 1;
#pragma unroll
    for (int ma = 0; ma < 2; ma++) {
        const int mloc = wm * 32 + ma * 16 + er;
#pragma unroll
        for (int na = 0; na < 4; na++) {
            const int nloc = wn * 32 + na * 8 + ec;
            float b0 = 0.0f, b1 = 0.0f;
            if (bias) { b0 = bias[n0 + nloc]; b1 = bias[n0 + nloc + 1]; }
            cs[nloc * CPITCH + mloc]           = acc[ma][na][0] + b0;
            cs[(nloc + 1) * CPITCH + mloc]     = acc[ma][na][1] + b1;
            cs[nloc * CPITCH + mloc + 8]       = acc[ma][na][2] + b0;
            cs[(nloc + 1) * CPITCH + mloc + 8] = acc[ma][na][3] + b1;
        }
    }
    __syncthreads();
    // 64 rows x 32 float4 = 2048 float4, 8 per thread, fully coalesced in CT
#pragma unroll
    for (int e = 0; e < 8; e++) {
        const int idx = tid + e * 256;
        const int nloc = idx >> 5;
        const int ml = (idx & 31) << 2;
        const int m = m0 + ml;
        const float4 v = *reinterpret_cast<const float4*>(&cs[nloc * CPITCH + ml]);
        *reinterpret_cast<float4*>(
            &CT[((size_t)(m >> bshift) * BN + (n0 + nloc)) * (size_t)width
                + (m & wmask)]) = v;
    }
}

// One launch, 48 y-tiles: y<32 -> Uv (K=1024, longer, scheduled first),
// y>=32 -> Wh (K=512).
__global__ __launch_bounds__(256) void gemm_dual_T(
    const __nv_bfloat16* __restrict__ A0h, const __nv_bfloat16* __restrict__ A0l,
    const __nv_bfloat16* __restrict__ B0h, const __nv_bfloat16* __restrict__ B0l,
    float* __restrict__ C0T,                        // UvT
    const __nv_bfloat16* __restrict__ A1h, const __nv_bfloat16* __restrict__ A1l,
    const __nv_bfloat16* __restrict__ B1h, const __nv_bfloat16* __restrict__ B1l,
    const float* __restrict__ bias1, float* __restrict__ C1T)  // WhT
{
    extern __shared__ __nv_bfloat16 gsm[];
    if ((int)blockIdx.y < 32) {
        gemm_body_T(gsm, A0h, A0l, B0h, B0l, nullptr, C0T, FS, 7,
                    blockIdx.y * 128, blockIdx.x * 64);
    } else {
        gemm_body_T(gsm, A1h, A1l, B1h, B1l, bias1, C1T, QS, 6,
                    (blockIdx.y - 32) * 128, blockIdx.x * 64);
    }
}

// ---------------------------------------------------------------------------
// Fused energies + softmax, v-split for occupancy (R8, proven).
// Block: 512 threads = 16 warps. warp = (q 0..7, vhalf 0..1); lane owns
// v = vhalf*64 + 2*lane + {0,1}.
// ---------------------------------------------------------------------------
#define QT 8
#define ECH 32
#define NCHUNK (BN / ECH)

__global__ __launch_bounds__(512) void energy_softmax_kernel(
    const float* __restrict__ WhT, const float* __restrict__ UvT,
    const float* __restrict__ w,
    float* __restrict__ energies, float* __restrict__ weights,
    __nv_bfloat16* __restrict__ wt_hi, __nv_bfloat16* __restrict__ wt_lo)
{
    __shared__ alignas(16) float Cs[2][ECH][LV];
    __shared__ alignas(16) float As[2][ECH][QT];
    __shared__ float ws[BN];
    __shared__ alignas(16) float red[QT][LV];

    const int b = blockIdx.y;
    const int q0 = blockIdx.x * QT;
    const int tid = threadIdx.x;
    const int lane = tid & 31;
    const int wid = tid >> 5;
    const int ql = wid >> 1;
    const int vh = wid & 1;
    const int v0 = vh * 64 + 2 * lane;

    const float* AbT = WhT + (size_t)b * BN * LQ;
    const float* CbT = UvT + (size_t)b * BN * LV;

    for (int i = tid; i < BN; i += 512) ws[i] = w[i];

    auto issue = [&](int c) {
        const int buf = c & 1;
        const int n0 = c * ECH;
#pragma unroll
        for (int e = 0; e < 2; e++) {
            const int o = tid + e * 512;
            const int row = o >> 5, col = (o & 31) * 4;
            cpasync16(&Cs[buf][row][col], &CbT[(size_t)(n0 + row) * LV + col]);
        }
        if (tid < 64) {
            const int row = tid >> 1, half = tid & 1;
            cpasync16(&As[buf][row][half * 4],
                      &AbT[(size_t)(n0 + row) * LQ + q0 + half * 4]);
        }
        asm volatile("cp.async.commit_group;");
    };

    float acc0 = 0.0f, acc1 = 0.0f;

    issue(0);
    for (int c = 0; c < NCHUNK; c++) {
        if (c + 1 < NCHUNK) {
            issue(c + 1);
            asm volatile("cp.async.wait_group 1;" ::: "memory");
        } else {
            asm volatile("cp.async.wait_group 0;" ::: "memory");
        }
        __syncthreads();
        const int buf = c & 1;
        const int nb = c * ECH;
#pragma unroll
        for (int kk = 0; kk < ECH; kk++) {
            const float a = As[buf][kk][ql];
            const float wn = ws[nb + kk];
            const float2 cv = *reinterpret_cast<const float2*>(
                &Cs[buf][kk][v0]);
            acc0 += wn * tanh_fast(a + cv.x);
            acc1 += wn * tanh_fast(a + cv.y);
        }
        __syncthreads();
    }

    red[ql][v0] = acc0;
    red[ql][v0 + 1] = acc1;
    __syncthreads();

    if (vh == 0) {
        const float4 a4 = *reinterpret_cast<const float4*>(&red[ql][4 * lane]);
        float acc[4] = {a4.x, a4.y, a4.z, a4.w};

        float mx = fmaxf(fmaxf(acc[0], acc[1]), fmaxf(acc[2], acc[3]));
#pragma unroll
        for (int o = 16; o > 0; o >>= 1)
            mx = fmaxf(mx, __shfl_xor_sync(0xFFFFFFFFu, mx, o));
        float ex[4], s = 0.0f;
#pragma unroll
        for (int j = 0; j < 4; j++) { ex[j] = __expf(acc[j] - mx); s += ex[j]; }
#pragma unroll
        for (int o = 16; o > 0; o >>= 1)
            s += __shfl_xor_sync(0xFFFFFFFFu, s, o);
        const float inv = __fdividef(1.0f, s);

        const size_t row = (size_t)b * LQ + q0 + ql;
        const size_t off = row * LV + 4 * lane;

        float4 e4; e4.x = acc[0]; e4.y = acc[1]; e4.z = acc[2]; e4.w = acc[3];
        *reinterpret_cast<float4*>(&energies[off]) = e4;

        float wv[4];
#pragma unroll
        for (int j = 0; j < 4; j++) wv[j] = ex[j] * inv;
        float4 w4; w4.x = wv[0]; w4.y = wv[1]; w4.z = wv[2]; w4.w = wv[3];
        *reinterpret_cast<float4*>(&weights[off]) = w4;

        __nv_bfloat162 h01, h23, l01, l23;
        h01.x = __float2bfloat16(wv[0]); h01.y = __float2bfloat16(wv[1]);
        h23.x = __float2bfloat16(wv[2]); h23.y = __float2bfloat16(wv[3]);
        l01.x = __float2bfloat16(wv[0] - __bfloat162float(h01.x));
        l01.y = __float2bfloat16(wv[1] - __bfloat162float(h01.y));
        l23.x = __float2bfloat16(wv[2] - __bfloat162float(h23.x));
        l23.y = __float2bfloat16(wv[3] - __bfloat162float(h23.y));
        uint2 hh, ll;
        hh.x = *reinterpret_cast<uint32_t*>(&h01);
        hh.y = *reinterpret_cast<uint32_t*>(&h23);
        ll.x = *reinterpret_cast<uint32_t*>(&l01);
        ll.y = *reinterpret_cast<uint32_t*>(&l23);
        *reinterpret_cast<uint2*>(&wt_hi[off]) = hh;
        *reinterpret_cast<uint2*>(&wt_lo[off]) = ll;
    }
}

// ---------------------------------------------------------------------------
// Tensor-core aligned: out[b,q,QS+f] = sum_v weights[b,q,v] * vis[b,v,f]
// ---------------------------------------------------------------------------
#define WPITCH 136

__global__ __launch_bounds__(256) void aligned_tc_kernel(
    const __nv_bfloat16* __restrict__ wt_hi, const __nv_bfloat16* __restrict__ wt_lo,
    const __nv_bfloat16* __restrict__ vis_hi, const __nv_bfloat16* __restrict__ vis_lo,
    float* __restrict__ out_sem)
{
    extern __shared__ __nv_bfloat16 asm_[];
    __nv_bfloat16* Wh_s = asm_;
    __nv_bfloat16* Wl_s = asm_ + 64 * WPITCH;
    __nv_bfloat16* Vh_s = asm_ + 128 * WPITCH;
    __nv_bfloat16* Vl_s = asm_ + 256 * WPITCH;

    const int b = blockIdx.y;
    const int f0 = blockIdx.x * 128;
    const int tid = threadIdx.x;
    const int lane = tid & 31;
    const int wid = tid >> 5;
    const int wm = wid >> 2;
    const int wn = wid & 3;
    const int lq = lane >> 3;
    const int lr = lane & 7;

#pragma unroll
    for (int e = 0; e < 4; e++) {
        int idx = tid + e * 256;
        int row = idx >> 4, c = (idx & 15) * 8;
        cpasync16(&Wh_s[row * WPITCH + c], &wt_hi[((size_t)b * LQ + row) * LV + c]);
        cpasync16(&Wl_s[row * WPITCH + c], &wt_lo[((size_t)b * LQ + row) * LV + c]);
    }
#pragma unroll
    for (int e = 0; e < 8; e++) {
        int idx = tid + e * 256;
        int row = idx >> 4, c = (idx & 15) * 8;
        cpasync16(&Vh_s[row * WPITCH + c],
                  &vis_hi[((size_t)b * LV + row) * FS + f0 + c]);
        cpasync16(&Vl_s[row * WPITCH + c],
                  &vis_lo[((size_t)b * LV + row) * FS + f0 + c]);
    }
    asm volatile("cp.async.commit_group;");
    asm volatile("cp.async.wait_group 0;" ::: "memory");
    __syncthreads();

    float acc[2][4][4];
#pragma unroll
    for (int i = 0; i < 2; i++)
#pragma unroll
        for (int j = 0; j < 4; j++)
#pragma unroll
            for (int r = 0; r < 4; r++) acc[i][j][r] = 0.0f;

#pragma unroll
    for (int ks = 0; ks < 8; ks++) {
        uint32_t ah[2][4], al[2][4];
#pragma unroll
        for (int ma = 0; ma < 2; ma++) {
            const int m_local = wm * 32 + ma * 16 + (lq & 1) * 8 + lr;
            const int k_local = ks * 16 + (lq >> 1) * 8;
            ldsm_x4(ah[ma][0], ah[ma][1], ah[ma][2], ah[ma][3],
                    smem_u32(&Wh_s[m_local * WPITCH + k_local]));
            ldsm_x4(al[ma][0], al[ma][1], al[ma][2], al[ma][3],
                    smem_u32(&Wl_s[m_local * WPITCH + k_local]));
        }
        uint32_t bh[4][2], bl[4][2];
#pragma unroll
        for (int np = 0; np < 2; np++) {
            const int krow = ks * 16 + (lq & 1) * 8 + lr;
            const int ncol = wn * 32 + np * 16 + (lq >> 1) * 8;
            uint32_t r0, r1, r2, r3;
            ldsm_x4_t(r0, r1, r2, r3, smem_u32(&Vh_s[krow * WPITCH + ncol]));
            bh[np * 2][0] = r0; bh[np * 2][1] = r1;
            bh[np * 2 + 1][0] = r2; bh[np * 2 + 1][1] = r3;
            ldsm_x4_t(r0, r1, r2, r3, smem_u32(&Vl_s[krow * WPITCH + ncol]));
            bl[np * 2][0] = r0; bl[np * 2][1] = r1;
            bl[np * 2 + 1][0] = r2; bl[np * 2 + 1][1] = r3;
        }
#pragma unroll
        for (int ma = 0; ma < 2; ma++)
#pragma unroll
            for (int na = 0; na < 4; na++) {
                mma_bf16(acc[ma][na], ah[ma], bh[na]);
                mma_bf16(acc[ma][na], ah[ma], bl[na]);
                mma_bf16(acc[ma][na], al[ma], bh[na]);
            }
    }

    const int er = lane >> 2;
    const int ec = (lane & 3) << 1;
#pragma unroll
    for (int ma = 0; ma < 2; ma++) {
        const int qbase = wm * 32 + ma * 16;
#pragma unroll
        for (int na = 0; na < 4; na++) {
            const int f = f0 + wn * 32 + na * 8 + ec;
            float2 v0, v1;
            v0.x = acc[ma][na][0]; v0.y = acc[ma][na][1];
            v1.x = acc[ma][na][2]; v1.y = acc[ma][na][3];
            *reinterpret_cast<float2*>(
                &out_sem[((size_t)b * LQ + qbase + er) * (QS + FS) + QS + f]) = v0;
            *reinterpret_cast<float2*>(
                &out_sem[((size_t)b * LQ + qbase + er + 8) * (QS + FS) + QS + f]) = v1;
        }
    }
}

extern "C" void kernel_launch(void* const* d_in, const int* in_sizes, int n_in,
                              void* d_out, int out_size)
{
    const float* phr  = (const float*)d_in[0];
    const float* vis  = (const float*)d_in[1];
    const float* W    = (const float*)d_in[2];
    const float* U    = (const float*)d_in[3];
    const float* bias = (const float*)d_in[4];
    const float* w    = (const float*)d_in[5];

    float* out = (float*)d_out;
    float* out_sem = out;
    float* out_w   = out + (size_t)NB * LQ * (QS + FS);
    float* out_e   = out_w + (size_t)NB * LQ * LV;

    float *WhT, *UvT;
    __nv_bfloat16 *phr_hi, *phr_lo, *vis_hi, *vis_lo, *W_hi, *W_lo, *U_hi, *U_lo;
    __nv_bfloat16 *wt_hi, *wt_lo;
    cudaGetSymbolAddress((void**)&WhT, g_WhT);
    cudaGetSymbolAddress((void**)&UvT, g_UvT);
    cudaGetSymbolAddress((void**)&phr_hi, g_phr_hi);
    cudaGetSymbolAddress((void**)&phr_lo, g_phr_lo);
    cudaGetSymbolAddress((void**)&vis_hi, g_vis_hi);
    cudaGetSymbolAddress((void**)&vis_lo, g_vis_lo);
    cudaGetSymbolAddress((void**)&W_hi, g_W_hi);
    cudaGetSymbolAddress((void**)&W_lo, g_W_lo);
    cudaGetSymbolAddress((void**)&U_hi, g_U_hi);
    cudaGetSymbolAddress((void**)&U_lo, g_U_lo);
    cudaGetSymbolAddress((void**)&wt_hi, g_wt_hi);
    cudaGetSymbolAddress((void**)&wt_lo, g_wt_lo);

    // 2 stages x 384 rows x 72 halves x 2 B = 110,592 B
    cudaFuncSetAttribute(gemm_dual_T,
                         cudaFuncAttributeMaxDynamicSharedMemorySize, 110592);
    cudaFuncSetAttribute(aligned_tc_kernel,
                         cudaFuncAttributeMaxDynamicSharedMemorySize, 104448);

    // split (+ phr concat copy)
    split4_kernel<<<5888, 256>>>(phr, phr_hi, phr_lo, 262144,
                                 vis, vis_hi, vis_lo, 1048576,
                                 W,   W_hi,   W_lo,   65536,
                                 U,   U_hi,   U_lo,   131072,
                                 out_sem);

    // Both GEMMs, one launch, 128x64 tiles, KC=64, 2-stage pipeline
    // (Uv: y 0..31, K=1024; Wh: y 32..47, K=512; x: 8 n-tiles)
    gemm_dual_T<<<dim3(BN / 64, 48), 256, 110592>>>(
        vis_hi, vis_lo, U_hi, U_lo, UvT,
        phr_hi, phr_lo, W_hi, W_lo, bias, WhT);

    // energies + softmax (v-split, 512 threads)
    energy_softmax_kernel<<<dim3(LQ / QT, NB), 512>>>(WhT, UvT, w, out_e, out_w,
                                                      wt_hi, wt_lo);
    // aligned via tensor cores
    aligned_tc_kernel<<<dim3(FS / 128, NB), 256, 104448>>>(wt_hi, wt_lo,
                                                           vis_hi, vis_lo,
                                                           out_sem);
}

// round 14
// speedup vs baseline: 1.1593x; 1.0061x over previous
#include <cuda_runtime.h>
#include <cuda_bf16.h>
#include <cstdint>
#include <cstddef>

#define NB 32
#define LQ 64
#define LV 128
#define QS 512
#define FS 1024
#define BN 512

// ---------------- scratch (device globals — no allocation) ----------------
// Wh/Uv stored TRANSPOSED per batch: WhT[b][n][q], UvT[b][n][v]
__device__ float g_WhT[(size_t)NB * BN * LQ];
__device__ float g_UvT[(size_t)NB * BN * LV];
__device__ __nv_bfloat16 g_phr_hi[(size_t)NB * LQ * QS];
__device__ __nv_bfloat16 g_phr_lo[(size_t)NB * LQ * QS];
__device__ __nv_bfloat16 g_vis_hi[(size_t)NB * LV * FS];
__device__ __nv_bfloat16 g_vis_lo[(size_t)NB * LV * FS];
__device__ __nv_bfloat16 g_W_hi[(size_t)BN * QS];
__device__ __nv_bfloat16 g_W_lo[(size_t)BN * QS];
__device__ __nv_bfloat16 g_U_hi[(size_t)BN * FS];
__device__ __nv_bfloat16 g_U_lo[(size_t)BN * FS];
__device__ __nv_bfloat16 g_wt_hi[(size_t)NB * LQ * LV];
__device__ __nv_bfloat16 g_wt_lo[(size_t)NB * LQ * LV];

// ---------------------------------------------------------------------------
// Helpers
// ---------------------------------------------------------------------------
__device__ __forceinline__ uint32_t smem_u32(const void* p) {
    return (uint32_t)__cvta_generic_to_shared(p);
}

__device__ __forceinline__ void cpasync16(void* s, const void* g) {
    asm volatile("cp.async.cg.shared.global [%0], [%1], 16;"
                 :: "r"(smem_u32(s)), "l"(g));
}

__device__ __forceinline__ void ldsm_x4(uint32_t& r0, uint32_t& r1,
                                        uint32_t& r2, uint32_t& r3, uint32_t addr) {
    asm volatile("ldmatrix.sync.aligned.m8n8.x4.shared.b16 {%0,%1,%2,%3}, [%4];"
                 : "=r"(r0), "=r"(r1), "=r"(r2), "=r"(r3) : "r"(addr));
}

__device__ __forceinline__ void ldsm_x4_t(uint32_t& r0, uint32_t& r1,
                                          uint32_t& r2, uint32_t& r3, uint32_t addr) {
    asm volatile("ldmatrix.sync.aligned.m8n8.x4.trans.shared.b16 {%0,%1,%2,%3}, [%4];"
                 : "=r"(r0), "=r"(r1), "=r"(r2), "=r"(r3) : "r"(addr));
}

__device__ __forceinline__ void mma_bf16(float* d, const uint32_t* a, const uint32_t* b) {
    asm volatile(
        "mma.sync.aligned.m16n8k16.row.col.f32.bf16.bf16.f32 "
        "{%0,%1,%2,%3}, {%4,%5,%6,%7}, {%8,%9}, {%0,%1,%2,%3};"
        : "+f"(d[0]), "+f"(d[1]), "+f"(d[2]), "+f"(d[3])
        : "r"(a[0]), "r"(a[1]), "r"(a[2]), "r"(a[3]), "r"(b[0]), "r"(b[1]));
}

// Hardware tanh: 1 MUFU op, rel err ~2^-11 (validated: net rel_err 5e-6)
__device__ __forceinline__ float tanh_fast(float x) {
    float y;
    asm("tanh.approx.f32 %0, %1;" : "=f"(y) : "f"(x));
    return y;
}

// ---------------------------------------------------------------------------
// Split pass: fp32 -> (hi, lo) bf16 for 4 arrays; also copies phr into the
// concat output columns [0, QS).
// ---------------------------------------------------------------------------
__global__ __launch_bounds__(256) void split4_kernel(
    const float* __restrict__ s0, __nv_bfloat16* __restrict__ h0, __nv_bfloat16* __restrict__ l0, int n0,
    const float* __restrict__ s1, __nv_bfloat16* __restrict__ h1, __nv_bfloat16* __restrict__ l1, int n1,
    const float* __restrict__ s2, __nv_bfloat16* __restrict__ h2, __nv_bfloat16* __restrict__ l2, int n2,
    const float* __restrict__ s3, __nv_bfloat16* __restrict__ h3, __nv_bfloat16* __restrict__ l3, int n3,
    float* __restrict__ out_sem)
{
    int i = blockIdx.x * 256 + threadIdx.x;
    const float* s; __nv_bfloat16 *h, *l; int idx;
    bool is_phr = false;
    if (i < n0)                { s = s0; h = h0; l = l0; idx = i; is_phr = true; }
    else if (i < n0 + n1)      { s = s1; h = h1; l = l1; idx = i - n0; }
    else if (i < n0 + n1 + n2) { s = s2; h = h2; l = l2; idx = i - n0 - n1; }
    else                       { s = s3; h = h3; l = l3; idx = i - n0 - n1 - n2; }

    float4 v = reinterpret_cast<const float4*>(s)[idx];
    __nv_bfloat162 ha, hb, la, lb;
    ha.x = __float2bfloat16(v.x); ha.y = __float2bfloat16(v.y);
    hb.x = __float2bfloat16(v.z); hb.y = __float2bfloat16(v.w);
    la.x = __float2bfloat16(v.x - __bfloat162float(ha.x));
    la.y = __float2bfloat16(v.y - __bfloat162float(ha.y));
    lb.x = __float2bfloat16(v.z - __bfloat162float(hb.x));
    lb.y = __float2bfloat16(v.w - __bfloat162float(hb.y));
    reinterpret_cast<__nv_bfloat162*>(h)[2 * idx]     = ha;
    reinterpret_cast<__nv_bfloat162*>(h)[2 * idx + 1] = hb;
    reinterpret_cast<__nv_bfloat162*>(l)[2 * idx]     = la;
    reinterpret_cast<__nv_bfloat162*>(l)[2 * idx + 1] = lb;

    if (is_phr) {
        const size_t row = (size_t)idx >> 7;
        const int col = (idx & 127) << 2;
        *reinterpret_cast<float4*>(&out_sem[row * (QS + FS) + col]) = v;
    }
}

// ---------------------------------------------------------------------------
// Tensor-core NT GEMM, 128x64 block tile, KC=64 chunks, cp.async 2-stage,
// B fragments via ldsm_x4. Transposed epilogue CT[b][n][m_local], staged
// through smem for coalesced float4 stores.
// 8 warps 4x2, warp tile 32x32, pinned 2 CTAs/SM.
// ---------------------------------------------------------------------------
#define APITCH 72               // 64 k + 8 pad halves (144 B rows, 16B-aligned)
#define KC 64
#define GSTAGE (384 * APITCH)   // Ah(128) Al(128) Bh(64) Bl(64) rows per stage
#define CPITCH 132              // epilogue staging pitch (floats)

__device__ __forceinline__ void gemm_issue_stage(
    __nv_bfloat16* smem, int st, int tid, int m0, int n0, int k0, int K,
    const __nv_bfloat16* Ahi, const __nv_bfloat16* Alo,
    const __nv_bfloat16* Bhi, const __nv_bfloat16* Blo)
{
    __nv_bfloat16* base = smem + st * GSTAGE;
    // A: 128 rows x 64 k = 1024 cp16 chunks each (hi, lo)
#pragma unroll
    for (int e = 0; e < 4; e++) {
        int idx = tid + e * 256;
        int row = idx >> 3, c = (idx & 7) * 8;
        cpasync16(&base[row * APITCH + c], &Ahi[(size_t)(m0 + row) * K + k0 + c]);
        cpasync16(&base[128 * APITCH + row * APITCH + c],
                  &Alo[(size_t)(m0 + row) * K + k0 + c]);
    }
    // B: 64 rows x 64 k = 512 cp16 chunks each (hi, lo)
#pragma unroll
    for (int e = 0; e < 2; e++) {
        int idx = tid + e * 256;
        int row = idx >> 3, c = (idx & 7) * 8;
        cpasync16(&base[256 * APITCH + row * APITCH + c],
                  &Bhi[(size_t)(n0 + row) * K + k0 + c]);
        cpasync16(&base[320 * APITCH + row * APITCH + c],
                  &Blo[(size_t)(n0 + row) * K + k0 + c]);
    }
    asm volatile("cp.async.commit_group;");
}

__device__ __forceinline__ void gemm_body_T(
    __nv_bfloat16* gsm,
    const __nv_bfloat16* __restrict__ Ahi, const __nv_bfloat16* __restrict__ Alo,
    const __nv_bfloat16* __restrict__ Bhi, const __nv_bfloat16* __restrict__ Blo,
    const float* __restrict__ bias, float* __restrict__ CT,
    int K, int bshift, int m0, int n0)
{
    const int tid = threadIdx.x;
    const int lane = tid & 31;
    const int wid = tid >> 5;
    const int wm = wid >> 1;
    const int wn = wid & 1;
    const int width = 1 << bshift;
    const int wmask = width - 1;

    const int lq = lane >> 3;
    const int lr = lane & 7;

    float acc[2][4][4];
#pragma unroll
    for (int i = 0; i < 2; i++)
#pragma unroll
        for (int j = 0; j < 4; j++)
#pragma unroll
            for (int r = 0; r < 4; r++) acc[i][j][r] = 0.0f;

    const int NC = K / KC;
    gemm_issue_stage(gsm, 0, tid, m0, n0, 0, K, Ahi, Alo, Bhi, Blo);

    for (int c = 0; c < NC; c++) {
        const int st = c & 1;
        if (c + 1 < NC) {
            gemm_issue_stage(gsm, st ^ 1, tid, m0, n0, (c + 1) * KC, K,
                             Ahi, Alo, Bhi, Blo);
            asm volatile("cp.async.wait_group 1;" ::: "memory");
        } else {
            asm volatile("cp.async.wait_group 0;" ::: "memory");
        }
        __syncthreads();

        const __nv_bfloat16* Ah_s = gsm + st * GSTAGE;
        const __nv_bfloat16* Al_s = Ah_s + 128 * APITCH;
        const __nv_bfloat16* Bh_s = Ah_s + 256 * APITCH;
        const __nv_bfloat16* Bl_s = Ah_s + 320 * APITCH;

#pragma unroll
        for (int ks = 0; ks < KC; ks += 16) {
            uint32_t ah[2][4], al[2][4];
#pragma unroll
            for (int ma = 0; ma < 2; ma++) {
                const int m_local = wm * 32 + ma * 16 + (lq & 1) * 8 + lr;
                const int k_local = ks + (lq >> 1) * 8;
                ldsm_x4(ah[ma][0], ah[ma][1], ah[ma][2], ah[ma][3],
                        smem_u32(&Ah_s[m_local * APITCH + k_local]));
                ldsm_x4(al[ma][0], al[ma][1], al[ma][2], al[ma][3],
                        smem_u32(&Al_s[m_local * APITCH + k_local]));
            }
            // B: 4 n-groups of 8; one ldsm_x4 covers 2 n-groups x 2 k-halves
            uint32_t bh[4][2], bl[4][2];
#pragma unroll
            for (int nb = 0; nb < 2; nb++) {
                const int n_local = wn * 32 + nb * 16 + (lq >> 1) * 8 + lr;
                const int k_local = ks + (lq & 1) * 8;
                uint32_t r0, r1, r2, r3;
                ldsm_x4(r0, r1, r2, r3,
                        smem_u32(&Bh_s[n_local * APITCH + k_local]));
                bh[2 * nb][0] = r0; bh[2 * nb][1] = r1;
                bh[2 * nb + 1][0] = r2; bh[2 * nb + 1][1] = r3;
                ldsm_x4(r0, r1, r2, r3,
                        smem_u32(&Bl_s[n_local * APITCH + k_local]));
                bl[2 * nb][0] = r0; bl[2 * nb][1] = r1;
                bl[2 * nb + 1][0] = r2; bl[2 * nb + 1][1] = r3;
            }
#pragma unroll
            for (int ma = 0; ma < 2; ma++)
#pragma unroll
                for (int na = 0; na < 4; na++) {
                    mma_bf16(acc[ma][na], ah[ma], bh[na]);
                    mma_bf16(acc[ma][na], ah[ma], bl[na]);
                    mma_bf16(acc[ma][na], al[ma], bh[na]);
                }
        }
        __syncthreads();
    }

    // --- epilogue: stage C tile [64 n][128 m] in smem, store coalesced ---
    float* cs = reinterpret_cast<float*>(gsm);   // 64 x CPITCH floats (~34 KB)
    const int er = lane >> 2;
    const int ec = (lane & 3) << 1;
#pragma unroll
    for (int ma = 0; ma < 2; ma++) {
        const int mloc = wm * 32 + ma * 16 + er;
#pragma unroll
        for (int na = 0; na < 4; na++) {
            const int nloc = wn * 32 + na * 8 + ec;
            float b0 = 0.0f, b1 = 0.0f;
            if (bias) { b0 = bias[n0 + nloc]; b1 = bias[n0 + nloc + 1]; }
            cs[nloc * CPITCH + mloc]           = acc[ma][na][0] + b0;
            cs[(nloc + 1) * CPITCH + mloc]     = acc[ma][na][1] + b1;
            cs[nloc * CPITCH + mloc + 8]       = acc[ma][na][2] + b0;
            cs[(nloc + 1) * CPITCH + mloc + 8] = acc[ma][na][3] + b1;
        }
    }
    __syncthreads();
    // 64 rows x 32 float4 = 2048 float4, 8 per thread, fully coalesced in CT
#pragma unroll
    for (int e = 0; e < 8; e++) {
        const int idx = tid + e * 256;
        const int nloc = idx >> 5;
        const int ml = (idx & 31) << 2;
        const int m = m0 + ml;
        const float4 v = *reinterpret_cast<const float4*>(&cs[nloc * CPITCH + ml]);
        *reinterpret_cast<float4*>(
            &CT[((size_t)(m >> bshift) * BN + (n0 + nloc)) * (size_t)width
                + (m & wmask)]) = v;
    }
}

// One launch, 48 y-tiles: y<32 -> Uv (K=1024, longer, scheduled first),
// y>=32 -> Wh (K=512). Pinned 2 CTAs/SM (regs <= 128).
__global__ __launch_bounds__(256, 2) void gemm_dual_T(
    const __nv_bfloat16* __restrict__ A0h, const __nv_bfloat16* __restrict__ A0l,
    const __nv_bfloat16* __restrict__ B0h, const __nv_bfloat16* __restrict__ B0l,
    float* __restrict__ C0T,                        // UvT
    const __nv_bfloat16* __restrict__ A1h, const __nv_bfloat16* __restrict__ A1l,
    const __nv_bfloat16* __restrict__ B1h, const __nv_bfloat16* __restrict__ B1l,
    const float* __restrict__ bias1, float* __restrict__ C1T)  // WhT
{
    extern __shared__ __nv_bfloat16 gsm[];
    if ((int)blockIdx.y < 32) {
        gemm_body_T(gsm, A0h, A0l, B0h, B0l, nullptr, C0T, FS, 7,
                    blockIdx.y * 128, blockIdx.x * 64);
    } else {
        gemm_body_T(gsm, A1h, A1l, B1h, B1l, bias1, C1T, QS, 6,
                    (blockIdx.y - 32) * 128, blockIdx.x * 64);
    }
}

// ---------------------------------------------------------------------------
// Fused energies + softmax, v-split for occupancy (proven).
// Block: 512 threads = 16 warps. warp = (q 0..7, vhalf 0..1); lane owns
// v = vhalf*64 + 2*lane + {0,1}.
// ---------------------------------------------------------------------------
#define QT 8
#define ECH 32
#define NCHUNK (BN / ECH)

__global__ __launch_bounds__(512) void energy_softmax_kernel(
    const float* __restrict__ WhT, const float* __restrict__ UvT,
    const float* __restrict__ w,
    float* __restrict__ energies, float* __restrict__ weights,
    __nv_bfloat16* __restrict__ wt_hi, __nv_bfloat16* __restrict__ wt_lo)
{
    __shared__ alignas(16) float Cs[2][ECH][LV];
    __shared__ alignas(16) float As[2][ECH][QT];
    __shared__ float ws[BN];
    __shared__ alignas(16) float red[QT][LV];

    const int b = blockIdx.y;
    const int q0 = blockIdx.x * QT;
    const int tid = threadIdx.x;
    const int lane = tid & 31;
    const int wid = tid >> 5;
    const int ql = wid >> 1;
    const int vh = wid & 1;
    const int v0 = vh * 64 + 2 * lane;

    const float* AbT = WhT + (size_t)b * BN * LQ;
    const float* CbT = UvT + (size_t)b * BN * LV;

    for (int i = tid; i < BN; i += 512) ws[i] = w[i];

    auto issue = [&](int c) {
        const int buf = c & 1;
        const int n0 = c * ECH;
#pragma unroll
        for (int e = 0; e < 2; e++) {
            const int o = tid + e * 512;
            const int row = o >> 5, col = (o & 31) * 4;
            cpasync16(&Cs[buf][row][col], &CbT[(size_t)(n0 + row) * LV + col]);
        }
        if (tid < 64) {
            const int row = tid >> 1, half = tid & 1;
            cpasync16(&As[buf][row][half * 4],
                      &AbT[(size_t)(n0 + row) * LQ + q0 + half * 4]);
        }
        asm volatile("cp.async.commit_group;");
    };

    float acc0 = 0.0f, acc1 = 0.0f;

    issue(0);
    for (int c = 0; c < NCHUNK; c++) {
        if (c + 1 < NCHUNK) {
            issue(c + 1);
            asm volatile("cp.async.wait_group 1;" ::: "memory");
        } else {
            asm volatile("cp.async.wait_group 0;" ::: "memory");
        }
        __syncthreads();
        const int buf = c & 1;
        const int nb = c * ECH;
#pragma unroll
        for (int kk = 0; kk < ECH; kk++) {
            const float a = As[buf][kk][ql];
            const float wn = ws[nb + kk];
            const float2 cv = *reinterpret_cast<const float2*>(
                &Cs[buf][kk][v0]);
            acc0 += wn * tanh_fast(a + cv.x);
            acc1 += wn * tanh_fast(a + cv.y);
        }
        __syncthreads();
    }

    red[ql][v0] = acc0;
    red[ql][v0 + 1] = acc1;
    __syncthreads();

    if (vh == 0) {
        const float4 a4 = *reinterpret_cast<const float4*>(&red[ql][4 * lane]);
        float acc[4] = {a4.x, a4.y, a4.z, a4.w};

        float mx = fmaxf(fmaxf(acc[0], acc[1]), fmaxf(acc[2], acc[3]));
#pragma unroll
        for (int o = 16; o > 0; o >>= 1)
            mx = fmaxf(mx, __shfl_xor_sync(0xFFFFFFFFu, mx, o));
        float ex[4], s = 0.0f;
#pragma unroll
        for (int j = 0; j < 4; j++) { ex[j] = __expf(acc[j] - mx); s += ex[j]; }
#pragma unroll
        for (int o = 16; o > 0; o >>= 1)
            s += __shfl_xor_sync(0xFFFFFFFFu, s, o);
        const float inv = __fdividef(1.0f, s);

        const size_t row = (size_t)b * LQ + q0 + ql;
        const size_t off = row * LV + 4 * lane;

        float4 e4; e4.x = acc[0]; e4.y = acc[1]; e4.z = acc[2]; e4.w = acc[3];
        *reinterpret_cast<float4*>(&energies[off]) = e4;

        float wv[4];
#pragma unroll
        for (int j = 0; j < 4; j++) wv[j] = ex[j] * inv;
        float4 w4; w4.x = wv[0]; w4.y = wv[1]; w4.z = wv[2]; w4.w = wv[3];
        *reinterpret_cast<float4*>(&weights[off]) = w4;

        __nv_bfloat162 h01, h23, l01, l23;
        h01.x = __float2bfloat16(wv[0]); h01.y = __float2bfloat16(wv[1]);
        h23.x = __float2bfloat16(wv[2]); h23.y = __float2bfloat16(wv[3]);
        l01.x = __float2bfloat16(wv[0] - __bfloat162float(h01.x));
        l01.y = __float2bfloat16(wv[1] - __bfloat162float(h01.y));
        l23.x = __float2bfloat16(wv[2] - __bfloat162float(h23.x));
        l23.y = __float2bfloat16(wv[3] - __bfloat162float(h23.y));
        uint2 hh, ll;
        hh.x = *reinterpret_cast<uint32_t*>(&h01);
        hh.y = *reinterpret_cast<uint32_t*>(&h23);
        ll.x = *reinterpret_cast<uint32_t*>(&l01);
        ll.y = *reinterpret_cast<uint32_t*>(&l23);
        *reinterpret_cast<uint2*>(&wt_hi[off]) = hh;
        *reinterpret_cast<uint2*>(&wt_lo[off]) = ll;
    }
}

// ---------------------------------------------------------------------------
// Tensor-core aligned: out[b,q,QS+f] = sum_v weights[b,q,v] * vis[b,v,f]
// ---------------------------------------------------------------------------
#define WPITCH 136

__global__ __launch_bounds__(256) void aligned_tc_kernel(
    const __nv_bfloat16* __restrict__ wt_hi, const __nv_bfloat16* __restrict__ wt_lo,
    const __nv_bfloat16* __restrict__ vis_hi, const __nv_bfloat16* __restrict__ vis_lo,
    float* __restrict__ out_sem)
{
    extern __shared__ __nv_bfloat16 asm_[];
    __nv_bfloat16* Wh_s = asm_;
    __nv_bfloat16* Wl_s = asm_ + 64 * WPITCH;
    __nv_bfloat16* Vh_s = asm_ + 128 * WPITCH;
    __nv_bfloat16* Vl_s = asm_ + 256 * WPITCH;

    const int b = blockIdx.y;
    const int f0 = blockIdx.x * 128;
    const int tid = threadIdx.x;
    const int lane = tid & 31;
    const int wid = tid >> 5;
    const int wm = wid >> 2;
    const int wn = wid & 3;
    const int lq = lane >> 3;
    const int lr = lane & 7;

#pragma unroll
    for (int e = 0; e < 4; e++) {
        int idx = tid + e * 256;
        int row = idx >> 4, c = (idx & 15) * 8;
        cpasync16(&Wh_s[row * WPITCH + c], &wt_hi[((size_t)b * LQ + row) * LV + c]);
        cpasync16(&Wl_s[row * WPITCH + c], &wt_lo[((size_t)b * LQ + row) * LV + c]);
    }
#pragma unroll
    for (int e = 0; e < 8; e++) {
        int idx = tid + e * 256;
        int row = idx >> 4, c = (idx & 15) * 8;
        cpasync16(&Vh_s[row * WPITCH + c],
                  &vis_hi[((size_t)b * LV + row) * FS + f0 + c]);
        cpasync16(&Vl_s[row * WPITCH + c],
                  &vis_lo[((size_t)b * LV + row) * FS + f0 + c]);
    }
    asm volatile("cp.async.commit_group;");
    asm volatile("cp.async.wait_group 0;" ::: "memory");
    __syncthreads();

    float acc[2][4][4];
#pragma unroll
    for (int i = 0; i < 2; i++)
#pragma unroll
        for (int j = 0; j < 4; j++)
#pragma unroll
            for (int r = 0; r < 4; r++) acc[i][j][r] = 0.0f;

#pragma unroll
    for (int ks = 0; ks < 8; ks++) {
        uint32_t ah[2][4], al[2][4];
#pragma unroll
        for (int ma = 0; ma < 2; ma++) {
            const int m_local = wm * 32 + ma * 16 + (lq & 1) * 8 + lr;
            const int k_local = ks * 16 + (lq >> 1) * 8;
            ldsm_x4(ah[ma][0], ah[ma][1], ah[ma][2], ah[ma][3],
                    smem_u32(&Wh_s[m_local * WPITCH + k_local]));
            ldsm_x4(al[ma][0], al[ma][1], al[ma][2], al[ma][3],
                    smem_u32(&Wl_s[m_local * WPITCH + k_local]));
        }
        uint32_t bh[4][2], bl[4][2];
#pragma unroll
        for (int np = 0; np < 2; np++) {
            const int krow = ks * 16 + (lq & 1) * 8 + lr;
            const int ncol = wn * 32 + np * 16 + (lq >> 1) * 8;
            uint32_t r0, r1, r2, r3;
            ldsm_x4_t(r0, r1, r2, r3, smem_u32(&Vh_s[krow * WPITCH + ncol]));
            bh[np * 2][0] = r0; bh[np * 2][1] = r1;
            bh[np * 2 + 1][0] = r2; bh[np * 2 + 1][1] = r3;
            ldsm_x4_t(r0, r1, r2, r3, smem_u32(&Vl_s[krow * WPITCH + ncol]));
            bl[np * 2][0] = r0; bl[np * 2][1] = r1;
            bl[np * 2 + 1][0] = r2; bl[np * 2 + 1][1] = r3;
        }
#pragma unroll
        for (int ma = 0; ma < 2; ma++)
#pragma unroll
            for (int na = 0; na < 4; na++) {
                mma_bf16(acc[ma][na], ah[ma], bh[na]);
                mma_bf16(acc[ma][na], ah[ma], bl[na]);
                mma_bf16(acc[ma][na], al[ma], bh[na]);
            }
    }

    const int er = lane >> 2;
    const int ec = (lane & 3) << 1;
#pragma unroll
    for (int ma = 0; ma < 2; ma++) {
        const int qbase = wm * 32 + ma * 16;
#pragma unroll
        for (int na = 0; na < 4; na++) {
            const int f = f0 + wn * 32 + na * 8 + ec;
            float2 v0, v1;
            v0.x = acc[ma][na][0]; v0.y = acc[ma][na][1];
            v1.x = acc[ma][na][2]; v1.y = acc[ma][na][3];
            *reinterpret_cast<float2*>(
                &out_sem[((size_t)b * LQ + qbase + er) * (QS + FS) + QS + f]) = v0;
            *reinterpret_cast<float2*>(
                &out_sem[((size_t)b * LQ + qbase + er + 8) * (QS + FS) + QS + f]) = v1;
        }
    }
}

extern "C" void kernel_launch(void* const* d_in, const int* in_sizes, int n_in,
                              void* d_out, int out_size)
{
    const float* phr  = (const float*)d_in[0];
    const float* vis  = (const float*)d_in[1];
    const float* W    = (const float*)d_in[2];
    const float* U    = (const float*)d_in[3];
    const float* bias = (const float*)d_in[4];
    const float* w    = (const float*)d_in[5];

    float* out = (float*)d_out;
    float* out_sem = out;
    float* out_w   = out + (size_t)NB * LQ * (QS + FS);
    float* out_e   = out_w + (size_t)NB * LQ * LV;

    float *WhT, *UvT;
    __nv_bfloat16 *phr_hi, *phr_lo, *vis_hi, *vis_lo, *W_hi, *W_lo, *U_hi, *U_lo;
    __nv_bfloat16 *wt_hi, *wt_lo;
    cudaGetSymbolAddress((void**)&WhT, g_WhT);
    cudaGetSymbolAddress((void**)&UvT, g_UvT);
    cudaGetSymbolAddress((void**)&phr_hi, g_phr_hi);
    cudaGetSymbolAddress((void**)&phr_lo, g_phr_lo);
    cudaGetSymbolAddress((void**)&vis_hi, g_vis_hi);
    cudaGetSymbolAddress((void**)&vis_lo, g_vis_lo);
    cudaGetSymbolAddress((void**)&W_hi, g_W_hi);
    cudaGetSymbolAddress((void**)&W_lo, g_W_lo);
    cudaGetSymbolAddress((void**)&U_hi, g_U_hi);
    cudaGetSymbolAddress((void**)&U_lo, g_U_lo);
    cudaGetSymbolAddress((void**)&wt_hi, g_wt_hi);
    cudaGetSymbolAddress((void**)&wt_lo, g_wt_lo);

    // 2 stages x 384 rows x 72 halves x 2 B = 110,592 B; 2 CTAs/SM = 221 KB
    cudaFuncSetAttribute(gemm_dual_T,
                         cudaFuncAttributeMaxDynamicSharedMemorySize, 110592);
    cudaFuncSetAttribute(aligned_tc_kernel,
                         cudaFuncAttributeMaxDynamicSharedMemorySize, 104448);

    // split (+ phr concat copy)
    split4_kernel<<<5888, 256>>>(phr, phr_hi, phr_lo, 262144,
                                 vis, vis_hi, vis_lo, 1048576,
                                 W,   W_hi,   W_lo,   65536,
                                 U,   U_hi,   U_lo,   131072,
                                 out_sem);

    // Both GEMMs, one launch, 128x64 tiles, KC=64, 2-stage pipeline
    // (Uv: y 0..31, K=1024; Wh: y 32..47, K=512; x: 8 n-tiles)
    gemm_dual_T<<<dim3(BN / 64, 48), 256, 110592>>>(
        vis_hi, vis_lo, U_hi, U_lo, UvT,
        phr_hi, phr_lo, W_hi, W_lo, bias, WhT);

    // energies + softmax (v-split, 512 threads)
    energy_softmax_kernel<<<dim3(LQ / QT, NB), 512>>>(WhT, UvT, w, out_e, out_w,
                                                      wt_hi, wt_lo);
    // aligned via tensor cores
    aligned_tc_kernel<<<dim3(FS / 128, NB), 256, 104448>>>(wt_hi, wt_lo,
                                                           vis_hi, vis_lo,
                                                           out_sem);
}